// round 6
// baseline (speedup 1.0000x reference)
#include <cuda_runtime.h>
#include <math.h>

// ---------------- problem dims ----------------
#define Bn   256
#define Ln   512
#define Cn   32
#define NBn  4
#define SEGn 64
#define FREQn 8
#define STEPn 4
#define Dn   512
#define Hn   1024
#define FINn 2048
#define Fn   257       // rfft bins
#define K2P  528       // 2*F=514 padded to multiple of 16

// ---------------- scratch (device globals; no allocation allowed) ----------------
__device__ float g_xn   [(size_t)Bn*Ln*Cn];
__device__ float g_mean [Bn*Cn];
__device__ float g_std  [Bn*Cn];
__device__ float g_XfRe [(size_t)Bn*Fn*Cn];
__device__ float g_XfIm [(size_t)Bn*Fn*Cn];
__device__ float g_cos  [Fn*Ln];
__device__ float g_sin  [Fn*Ln];
__device__ float g_cf   [NBn*Fn];
__device__ float g_bas  [Ln*K2P];
__device__ float g_spec [(size_t)NBn*Bn*K2P*Cn];
__device__ float g_xi   [(size_t)NBn*Bn*Ln*Cn];
__device__ float g_enc1 [(size_t)NBn*Bn*FREQn*Hn];
__device__ float g_enc2 [(size_t)NBn*Bn*FREQn*Dn];
__device__ float g_encx [(size_t)NBn*Bn*FREQn*Dn];
__device__ float g_hA   [NBn*Bn*Dn];
__device__ float g_hB   [NBn*Bn*Dn];
__device__ float g_preds[NBn*Bn*STEPn*Dn];
__device__ float g_dec1 [(size_t)NBn*Bn*STEPn*Hn];
__device__ float g_dec2 [(size_t)NBn*Bn*STEPn*FINn];

// ---------------- tables: trig, irfft basis, sigmoid(mask) ----------------
__global__ void tables_k(const float* __restrict__ mw) {
    int i = blockIdx.x * 256 + threadIdx.x;
    const float STEPA = 6.28318530717958647692f / (float)Ln;  // 2*pi/512
    if (i < Fn * Ln) {
        int k = i >> 9, t = i & 511;
        int ph = (k * t) & (Ln - 1);
        float s, c;
        sincosf((float)ph * STEPA, &s, &c);
        g_cos[i] = c; g_sin[i] = s;
    }
    if (i < Ln * K2P) {
        int t = i / K2P, k2 = i % K2P;
        float v = 0.f;
        if (k2 < 2 * Fn) {
            int k = k2 >> 1;
            int ph = (k * t) & (Ln - 1);
            float ang = (float)ph * STEPA;
            float w = ((k == 0) || (k == Fn - 1)) ? 1.f : 2.f;
            w *= (1.f / (float)Ln);
            v = (k2 & 1) ? (-w * sinf(ang)) : (w * cosf(ang));
        }
        g_bas[i] = v;
    }
    if (i < NBn * Fn) {
        g_cf[i] = 1.f / (1.f + expf(-mw[i]));
    }
}

// ---------------- instance norm over time (stats per (b,c)) ----------------
__global__ void instnorm_k(const float* __restrict__ x) {
    int b = blockIdx.x;
    int c = threadIdx.x & 31, r = threadIdx.x >> 5;
    const float* xb = x + (size_t)b * Ln * Cn;
    float s = 0.f, sq = 0.f;
    for (int t = r; t < Ln; t += 8) {
        float v = xb[t * Cn + c];
        s += v; sq += v * v;
    }
    __shared__ float ss[8][32], sg[8][32];
    __shared__ float smean[32], srstd[32];
    ss[r][c] = s; sg[r][c] = sq;
    __syncthreads();
    if (threadIdx.x < 32) {
        float a = 0.f, q = 0.f;
        #pragma unroll
        for (int j = 0; j < 8; j++) { a += ss[j][threadIdx.x]; q += sg[j][threadIdx.x]; }
        float m  = a * (1.f / (float)Ln);
        float var = q * (1.f / (float)Ln) - m * m;
        float sd = sqrtf(var + 1e-5f);
        g_mean[b * Cn + threadIdx.x] = m;
        g_std [b * Cn + threadIdx.x] = sd;
        smean[threadIdx.x] = m;
        srstd[threadIdx.x] = 1.f / sd;
    }
    __syncthreads();
    float m = smean[c], rs = srstd[c];
    float* xo = g_xn + (size_t)b * Ln * Cn;
    for (int t = r; t < Ln; t += 8) {
        xo[t * Cn + c] = (xb[t * Cn + c] - m) * rs;
    }
}

// ---------------- forward DFT (rfft), even/odd symmetry folded ----------------
__global__ void dft_k() {
    int b = blockIdx.x;
    int warp = threadIdx.x >> 5, c = threadIdx.x & 31;
    const float* xb = g_xn + (size_t)b * Ln * Cn;
    float x0   = xb[c];
    float x256 = xb[256 * Cn + c];
    for (int k = warp; k < Fn; k += 8) {
        const float* tc = g_cos + (size_t)k * Ln;
        const float* ts = g_sin + (size_t)k * Ln;
        float re = x0 + ((k & 1) ? -x256 : x256);
        float im = 0.f;
        #pragma unroll 4
        for (int t = 1; t <= 255; t++) {
            float v1 = xb[t * Cn + c];
            float v2 = xb[(Ln - t) * Cn + c];
            re = fmaf(v1 + v2, tc[t], re);
            im = fmaf(v1 - v2, ts[t], im);
        }
        g_XfRe[((size_t)b * Fn + k) * Cn + c] = re;
        g_XfIm[((size_t)b * Fn + k) * Cn + c] = -im;
    }
}

// ---------------- build scaled spectrum [nb][b][k2][c] (mask folded in) ----------------
__global__ void spec_k() {
    int blk = blockIdx.x;
    int nb = blk >> 8, b = blk & 255;
    float* out = g_spec + (size_t)(nb * Bn + b) * K2P * Cn;
    const float* re = g_XfRe + (size_t)b * Fn * Cn;
    const float* im = g_XfIm + (size_t)b * Fn * Cn;
    for (int idx = threadIdx.x; idx < Fn * Cn; idx += blockDim.x) {
        int k = idx >> 5, c = idx & 31;
        float cf = g_cf[nb * Fn + k];
        out[(2 * k)     * Cn + c] = re[idx] * cf;
        out[(2 * k + 1) * Cn + c] = im[idx] * cf;
    }
    for (int idx = 2 * Fn * Cn + threadIdx.x; idx < K2P * Cn; idx += blockDim.x)
        out[idx] = 0.f;
}

// ---------------- generic tiled SGEMM: C = act(A @ op(W) + bias + E) ----------------
// A: [M,K] rows strided ldA.  WT=true: W is [N,K] ld=ldW.  WT=false: W is [K,N] ld=ldW.
// batch via blockIdx.z with strides sA/sW/sBias/sE/sC.
template<int BM, int BN, int TM, int TN, bool RELU, bool WT>
__global__ void __launch_bounds__((BM/TM)*(BN/TN))
gemm_k(const float* __restrict__ A, size_t sA, int ldA,
       const float* __restrict__ W, size_t sW, int ldW,
       const float* __restrict__ bias, int sBias,
       const float* __restrict__ E, size_t sE, int ldE,
       float* __restrict__ C, size_t sC, int ldC,
       int K)
{
    constexpr int BK = 16;
    constexpr int NT = (BM / TM) * (BN / TN);
    constexpr int A4 = BM * BK / 4;
    constexpr int W4 = BN * BK / 4;
    static_assert(A4 % NT == 0, "A load divisibility");
    static_assert(W4 % NT == 0 || NT % W4 == 0, "W load divisibility");

    __shared__ float As[BK][BM];
    __shared__ float Ws[BK][BN];

    int tid = threadIdx.x;
    int z = blockIdx.z;
    int m0 = blockIdx.y * BM, n0 = blockIdx.x * BN;

    A += z * sA + (size_t)m0 * ldA;
    W += z * sW;
    C += z * sC + (size_t)m0 * ldC + n0;
    if (E) E += z * sE + (size_t)m0 * ldE + n0;

    int tx = tid % (BN / TN), ty = tid / (BN / TN);
    float acc[TM][TN];
    #pragma unroll
    for (int i = 0; i < TM; i++)
        #pragma unroll
        for (int j = 0; j < TN; j++) acc[i][j] = 0.f;

    for (int k0 = 0; k0 < K; k0 += BK) {
        // load A tile -> As[k][m]
        #pragma unroll
        for (int j = 0; j < A4 / NT; j++) {
            int idx = tid + j * NT;
            int row = idx >> 2;
            int kq = (idx & 3) << 2;
            float4 v = *reinterpret_cast<const float4*>(A + (size_t)row * ldA + k0 + kq);
            As[kq + 0][row] = v.x; As[kq + 1][row] = v.y;
            As[kq + 2][row] = v.z; As[kq + 3][row] = v.w;
        }
        // load W tile -> Ws[k][n]
        #pragma unroll
        for (int j = 0; j < (W4 + NT - 1) / NT; j++) {
            int idx = tid + j * NT;
            if (W4 % NT != 0 && idx >= W4) break;
            if (WT) {
                int row = idx >> 2;            // n
                int kq = (idx & 3) << 2;
                float4 v = *reinterpret_cast<const float4*>(W + (size_t)(n0 + row) * ldW + k0 + kq);
                Ws[kq + 0][row] = v.x; Ws[kq + 1][row] = v.y;
                Ws[kq + 2][row] = v.z; Ws[kq + 3][row] = v.w;
            } else {
                constexpr int WPR = BN / 4;
                int row = idx / WPR;           // k
                int col = (idx % WPR) << 2;    // n
                float4 v = *reinterpret_cast<const float4*>(W + (size_t)(k0 + row) * ldW + n0 + col);
                *reinterpret_cast<float4*>(&Ws[row][col]) = v;
            }
        }
        __syncthreads();
        #pragma unroll
        for (int kk = 0; kk < BK; kk++) {
            float a[TM], w[TN];
            #pragma unroll
            for (int i = 0; i < TM; i++) a[i] = As[kk][ty * TM + i];
            #pragma unroll
            for (int j = 0; j < TN; j++) w[j] = Ws[kk][tx * TN + j];
            #pragma unroll
            for (int i = 0; i < TM; i++)
                #pragma unroll
                for (int j = 0; j < TN; j++)
                    acc[i][j] = fmaf(a[i], w[j], acc[i][j]);
        }
        __syncthreads();
    }

    float bv[TN];
    #pragma unroll
    for (int j = 0; j < TN; j++)
        bv[j] = bias ? bias[(size_t)z * sBias + n0 + tx * TN + j] : 0.f;

    #pragma unroll
    for (int i = 0; i < TM; i++) {
        float4 o;
        float* op = &o.x;
        #pragma unroll
        for (int j = 0; j < TN; j++) {
            float v = acc[i][j] + bv[j];
            if (E) v += E[(size_t)(ty * TM + i) * ldE + tx * TN + j];
            if (RELU) v = fmaxf(v, 0.f);
            op[j] = v;
        }
        *reinterpret_cast<float4*>(&C[(size_t)(ty * TM + i) * ldC + tx * TN]) = o;
    }
}

// ---------------- LayerNorm over D (in-place on g_preds) ----------------
__global__ void ln_k(const float* __restrict__ g, const float* __restrict__ bb) {
    int row = blockIdx.x;            // nb*B*STEP + b*STEP + s
    int nb = row >> 10;              // /(B*STEP)=1024
    float* p = g_preds + (size_t)row * Dn;
    int tid = threadIdx.x;           // 128 threads
    float v[4];
    float s = 0.f, sq = 0.f;
    #pragma unroll
    for (int j = 0; j < 4; j++) {
        v[j] = p[tid + j * 128];
        s += v[j]; sq += v[j] * v[j];
    }
    #pragma unroll
    for (int off = 16; off > 0; off >>= 1) {
        s  += __shfl_xor_sync(0xffffffffu, s, off);
        sq += __shfl_xor_sync(0xffffffffu, sq, off);
    }
    __shared__ float rs[4], rq[4];
    if ((tid & 31) == 0) { rs[tid >> 5] = s; rq[tid >> 5] = sq; }
    __syncthreads();
    s = rs[0] + rs[1] + rs[2] + rs[3];
    sq = rq[0] + rq[1] + rq[2] + rq[3];
    float mean = s * (1.f / (float)Dn);
    float var = sq * (1.f / (float)Dn) - mean * mean;
    float rstd = rsqrtf(var + 1e-5f);
    #pragma unroll
    for (int j = 0; j < 4; j++) {
        int d = tid + j * 128;
        p[d] = (v[j] - mean) * rstd * g[nb * Dn + d] + bb[nb * Dn + d];
    }
}

// ---------------- final: sum over blocks, de-normalize ----------------
__global__ void final_k(float* __restrict__ out) {
    size_t i = (size_t)blockIdx.x * 256 + threadIdx.x;
    const size_t TOT = (size_t)Bn * STEPn * SEGn * Cn;  // 2097152
    if (i >= TOT) return;
    int b = (int)(i >> 13);   // 8192 per b
    int c = (int)(i & 31);
    const size_t S = TOT;
    float a = g_dec2[i] + g_dec2[i + S] + g_dec2[i + 2 * S] + g_dec2[i + 3 * S];
    out[i] = a * g_std[b * Cn + c] + g_mean[b * Cn + c];
}

// ---------------- host launch ----------------
extern "C" void kernel_launch(void* const* d_in, const int* in_sizes, int n_in,
                              void* d_out, int out_size) {
    const float* x_enc = (const float*)d_in[0];
    const float* mw    = (const float*)d_in[4];
    const float* ew1   = (const float*)d_in[5];
    const float* eb1   = (const float*)d_in[6];
    const float* ew2   = (const float*)d_in[7];
    const float* eb2   = (const float*)d_in[8];
    const float* wxh   = (const float*)d_in[9];
    const float* whh   = (const float*)d_in[10];
    const float* lng   = (const float*)d_in[11];
    const float* lnb   = (const float*)d_in[12];
    const float* dw1   = (const float*)d_in[13];
    const float* db1   = (const float*)d_in[14];
    const float* dw2   = (const float*)d_in[15];
    const float* db2   = (const float*)d_in[16];
    float* out = (float*)d_out;

    float *p_bas, *p_spec, *p_xi, *p_enc1, *p_enc2, *p_encx, *p_hA, *p_hB, *p_preds, *p_dec1, *p_dec2;
    cudaGetSymbolAddress((void**)&p_bas,  g_bas);
    cudaGetSymbolAddress((void**)&p_spec, g_spec);
    cudaGetSymbolAddress((void**)&p_xi,   g_xi);
    cudaGetSymbolAddress((void**)&p_enc1, g_enc1);
    cudaGetSymbolAddress((void**)&p_enc2, g_enc2);
    cudaGetSymbolAddress((void**)&p_encx, g_encx);
    cudaGetSymbolAddress((void**)&p_hA,   g_hA);
    cudaGetSymbolAddress((void**)&p_hB,   g_hB);
    cudaGetSymbolAddress((void**)&p_preds,g_preds);
    cudaGetSymbolAddress((void**)&p_dec1, g_dec1);
    cudaGetSymbolAddress((void**)&p_dec2, g_dec2);

    tables_k  <<<(Ln * K2P + 255) / 256, 256>>>(mw);
    instnorm_k<<<Bn, 256>>>(x_enc);
    dft_k     <<<Bn, 256>>>();
    spec_k    <<<NBn * Bn, 256>>>();

    // masked irfft as batched GEMM: xi[nb,b] = Bas[512,528] @ spec[nb,b][528,32]
    gemm_k<64, 32, 4, 4, false, false><<<dim3(Cn / 32, Ln / 64, NBn * Bn), 128>>>(
        p_bas, 0, K2P,
        p_spec, (size_t)K2P * Cn, Cn,
        nullptr, 0,
        nullptr, 0, 0,
        p_xi, (size_t)Ln * Cn, Cn, K2P);

    // encoder L1: relu(xi @ ew1^T + eb1)
    gemm_k<64, 64, 4, 4, true, true><<<dim3(Hn / 64, (Bn * FREQn) / 64, NBn), 256>>>(
        p_xi, (size_t)Bn * Ln * Cn, FINn,
        ew1, (size_t)Hn * FINn, FINn,
        eb1, Hn,
        nullptr, 0, 0,
        p_enc1, (size_t)Bn * FREQn * Hn, Hn, FINn);

    // encoder L2
    gemm_k<64, 64, 4, 4, false, true><<<dim3(Dn / 64, (Bn * FREQn) / 64, NBn), 256>>>(
        p_enc1, (size_t)Bn * FREQn * Hn, Hn,
        ew2, (size_t)Dn * Hn, Hn,
        eb2, Dn,
        nullptr, 0, 0,
        p_enc2, (size_t)Bn * FREQn * Dn, Dn, Hn);

    // encx = enc @ Wxh^T (hoisted out of the scan)
    gemm_k<64, 64, 4, 4, false, true><<<dim3(Dn / 64, (Bn * FREQn) / 64, NBn), 256>>>(
        p_enc2, (size_t)Bn * FREQn * Dn, Dn,
        wxh, (size_t)Dn * Dn, Dn,
        nullptr, 0,
        nullptr, 0, 0,
        p_encx, (size_t)Bn * FREQn * Dn, Dn, Dn);

    // RNN recurrence: h_t = encx_t + h_{t-1} @ Whh^T   (h_0 = encx_0)
    for (int tau = 1; tau < FREQn; tau++) {
        const float* Ap; size_t sAv; int ldAv;
        if (tau == 1) { Ap = p_encx; sAv = (size_t)Bn * FREQn * Dn; ldAv = FREQn * Dn; }
        else if (tau % 2 == 0) { Ap = p_hA; sAv = (size_t)Bn * Dn; ldAv = Dn; }
        else { Ap = p_hB; sAv = (size_t)Bn * Dn; ldAv = Dn; }
        float* Cp = (tau % 2 == 1) ? p_hA : p_hB;
        gemm_k<64, 64, 4, 4, false, true><<<dim3(Dn / 64, Bn / 64, NBn), 256>>>(
            Ap, sAv, ldAv,
            whh, (size_t)Dn * Dn, Dn,
            nullptr, 0,
            p_encx + tau * Dn, (size_t)Bn * FREQn * Dn, FREQn * Dn,
            Cp, (size_t)Bn * Dn, Dn, Dn);
    }
    // free-run: preds_s = h @ (Whh^T)^(s+1)   (final h sits in g_hA)
    for (int s = 0; s < STEPn; s++) {
        const float* Ap; size_t sAv; int ldAv;
        if (s == 0) { Ap = p_hA; sAv = (size_t)Bn * Dn; ldAv = Dn; }
        else { Ap = p_preds + (s - 1) * Dn; sAv = (size_t)Bn * STEPn * Dn; ldAv = STEPn * Dn; }
        gemm_k<64, 64, 4, 4, false, true><<<dim3(Dn / 64, Bn / 64, NBn), 256>>>(
            Ap, sAv, ldAv,
            whh, (size_t)Dn * Dn, Dn,
            nullptr, 0,
            nullptr, 0, 0,
            p_preds + s * Dn, (size_t)Bn * STEPn * Dn, STEPn * Dn, Dn);
    }

    ln_k<<<NBn * Bn * STEPn, 128>>>(lng, lnb);

    // decoder L1: relu(preds @ dw1^T + db1)
    gemm_k<64, 64, 4, 4, true, true><<<dim3(Hn / 64, (Bn * STEPn) / 64, NBn), 256>>>(
        p_preds, (size_t)Bn * STEPn * Dn, Dn,
        dw1, (size_t)Hn * Dn, Dn,
        db1, Hn,
        nullptr, 0, 0,
        p_dec1, (size_t)Bn * STEPn * Hn, Hn, Dn);

    // decoder L2
    gemm_k<64, 64, 4, 4, false, true><<<dim3(FINn / 64, (Bn * STEPn) / 64, NBn), 256>>>(
        p_dec1, (size_t)Bn * STEPn * Hn, Hn,
        dw2, (size_t)FINn * Hn, Hn,
        db2, FINn,
        nullptr, 0, 0,
        p_dec2, (size_t)Bn * STEPn * FINn, FINn, Hn);

    final_k<<<(Bn * STEPn * SEGn * Cn + 255) / 256, 256>>>(out);
}

// round 7
// speedup vs baseline: 1.6148x; 1.6148x over previous
#include <cuda_runtime.h>
#include <math.h>

// ---------------- problem dims ----------------
#define Bn   256
#define Ln   512
#define Cn   32
#define NBn  4
#define SEGn 64
#define FREQn 8
#define STEPn 4
#define Dn   512
#define Hn   1024
#define FINn 2048
#define Fn   257       // rfft bins
#define K2P  528       // 2*F=514 padded to multiple of 16

// ---------------- scratch (device globals; no allocation allowed) ----------------
__device__ float g_xn   [(size_t)Bn*Ln*Cn];
__device__ float g_mean [Bn*Cn];
__device__ float g_std  [Bn*Cn];
__device__ float g_XfRe [(size_t)Bn*Fn*Cn];
__device__ float g_XfIm [(size_t)Bn*Fn*Cn];
__device__ float g_cos  [Fn*Ln];
__device__ float g_sin  [Fn*Ln];
__device__ float g_cf   [NBn*Fn];
__device__ float g_bas  [Ln*K2P];
__device__ float g_spec [(size_t)NBn*Bn*K2P*Cn];
__device__ float g_xi   [(size_t)NBn*Bn*Ln*Cn];
__device__ float g_enc1 [(size_t)NBn*Bn*FREQn*Hn];
__device__ float g_enc2 [(size_t)NBn*Bn*FREQn*Dn];
__device__ float g_encx [(size_t)NBn*Bn*FREQn*Dn];
__device__ float g_hA   [NBn*Bn*Dn];
__device__ float g_hB   [NBn*Bn*Dn];
__device__ float g_preds[NBn*Bn*STEPn*Dn];
__device__ float g_dec1 [(size_t)NBn*Bn*STEPn*Hn];
__device__ float g_dec2 [(size_t)NBn*Bn*STEPn*FINn];

// ---------------- tables: trig, irfft basis, sigmoid(mask) ----------------
__global__ void tables_k(const float* __restrict__ mw) {
    int i = blockIdx.x * 256 + threadIdx.x;
    const float STEPA = 6.28318530717958647692f / (float)Ln;  // 2*pi/512
    if (i < Fn * Ln) {
        int k = i >> 9, t = i & 511;
        int ph = (k * t) & (Ln - 1);
        float s, c;
        sincosf((float)ph * STEPA, &s, &c);
        g_cos[i] = c; g_sin[i] = s;
    }
    if (i < Ln * K2P) {
        int t = i / K2P, k2 = i % K2P;
        float v = 0.f;
        if (k2 < 2 * Fn) {
            int k = k2 >> 1;
            int ph = (k * t) & (Ln - 1);
            float ang = (float)ph * STEPA;
            float w = ((k == 0) || (k == Fn - 1)) ? 1.f : 2.f;
            w *= (1.f / (float)Ln);
            v = (k2 & 1) ? (-w * sinf(ang)) : (w * cosf(ang));
        }
        g_bas[i] = v;
    }
    if (i < NBn * Fn) {
        g_cf[i] = 1.f / (1.f + expf(-mw[i]));
    }
}

// ---------------- instance norm over time (stats per (b,c)) ----------------
__global__ void instnorm_k(const float* __restrict__ x) {
    int b = blockIdx.x;
    int c = threadIdx.x & 31, r = threadIdx.x >> 5;
    const float* xb = x + (size_t)b * Ln * Cn;
    float s = 0.f, sq = 0.f;
    for (int t = r; t < Ln; t += 8) {
        float v = xb[t * Cn + c];
        s += v; sq += v * v;
    }
    __shared__ float ss[8][32], sg[8][32];
    __shared__ float smean[32], srstd[32];
    ss[r][c] = s; sg[r][c] = sq;
    __syncthreads();
    if (threadIdx.x < 32) {
        float a = 0.f, q = 0.f;
        #pragma unroll
        for (int j = 0; j < 8; j++) { a += ss[j][threadIdx.x]; q += sg[j][threadIdx.x]; }
        float m  = a * (1.f / (float)Ln);
        float var = q * (1.f / (float)Ln) - m * m;
        float sd = sqrtf(var + 1e-5f);
        g_mean[b * Cn + threadIdx.x] = m;
        g_std [b * Cn + threadIdx.x] = sd;
        smean[threadIdx.x] = m;
        srstd[threadIdx.x] = 1.f / sd;
    }
    __syncthreads();
    float m = smean[c], rs = srstd[c];
    float* xo = g_xn + (size_t)b * Ln * Cn;
    for (int t = r; t < Ln; t += 8) {
        xo[t * Cn + c] = (xb[t * Cn + c] - m) * rs;
    }
}

// ---------------- forward DFT (rfft), even/odd symmetry folded ----------------
__global__ void dft_k() {
    int b = blockIdx.x;
    int warp = threadIdx.x >> 5, c = threadIdx.x & 31;
    const float* xb = g_xn + (size_t)b * Ln * Cn;
    float x0   = xb[c];
    float x256 = xb[256 * Cn + c];
    for (int k = warp; k < Fn; k += 8) {
        const float* tc = g_cos + (size_t)k * Ln;
        const float* ts = g_sin + (size_t)k * Ln;
        float re = x0 + ((k & 1) ? -x256 : x256);
        float im = 0.f;
        #pragma unroll 4
        for (int t = 1; t <= 255; t++) {
            float v1 = xb[t * Cn + c];
            float v2 = xb[(Ln - t) * Cn + c];
            re = fmaf(v1 + v2, tc[t], re);
            im = fmaf(v1 - v2, ts[t], im);
        }
        g_XfRe[((size_t)b * Fn + k) * Cn + c] = re;
        g_XfIm[((size_t)b * Fn + k) * Cn + c] = -im;
    }
}

// ---------------- build scaled spectrum [nb][b][k2][c] (mask folded in) ----------------
__global__ void spec_k() {
    int blk = blockIdx.x;
    int nb = blk >> 8, b = blk & 255;
    float* out = g_spec + (size_t)(nb * Bn + b) * K2P * Cn;
    const float* re = g_XfRe + (size_t)b * Fn * Cn;
    const float* im = g_XfIm + (size_t)b * Fn * Cn;
    for (int idx = threadIdx.x; idx < Fn * Cn; idx += blockDim.x) {
        int k = idx >> 5, c = idx & 31;
        float cf = g_cf[nb * Fn + k];
        out[(2 * k)     * Cn + c] = re[idx] * cf;
        out[(2 * k + 1) * Cn + c] = im[idx] * cf;
    }
    for (int idx = 2 * Fn * Cn + threadIdx.x; idx < K2P * Cn; idx += blockDim.x)
        out[idx] = 0.f;
}

// ---------------- generic tiled SGEMM: C = act(A @ op(W) + bias + E) ----------------
// A: [M,K] rows strided ldA.  WT=true: W is [N,K] ld=ldW.  WT=false: W is [K,N] ld=ldW.
// batch via blockIdx.z with strides sA/sW/sBias/sE/sC.
template<int BM, int BN, int TM, int TN, bool RELU, bool WT>
__global__ void __launch_bounds__((BM/TM)*(BN/TN))
gemm_k(const float* __restrict__ A, size_t sA, int ldA,
       const float* __restrict__ W, size_t sW, int ldW,
       const float* __restrict__ bias, int sBias,
       const float* __restrict__ E, size_t sE, int ldE,
       float* __restrict__ C, size_t sC, int ldC,
       int K)
{
    constexpr int BK = 16;
    constexpr int NT = (BM / TM) * (BN / TN);
    constexpr int A4 = BM * BK / 4;
    constexpr int W4 = BN * BK / 4;
    static_assert(A4 % NT == 0, "A load divisibility");
    static_assert(W4 % NT == 0 || NT % W4 == 0, "W load divisibility");

    __shared__ float As[BK][BM];
    __shared__ float Ws[BK][BN];

    int tid = threadIdx.x;
    int z = blockIdx.z;
    int m0 = blockIdx.y * BM, n0 = blockIdx.x * BN;

    A += z * sA + (size_t)m0 * ldA;
    W += z * sW;
    C += z * sC + (size_t)m0 * ldC + n0;
    if (E) E += z * sE + (size_t)m0 * ldE + n0;

    int tx = tid % (BN / TN), ty = tid / (BN / TN);
    float acc[TM][TN];
    #pragma unroll
    for (int i = 0; i < TM; i++)
        #pragma unroll
        for (int j = 0; j < TN; j++) acc[i][j] = 0.f;

    for (int k0 = 0; k0 < K; k0 += BK) {
        // load A tile -> As[k][m]
        #pragma unroll
        for (int j = 0; j < A4 / NT; j++) {
            int idx = tid + j * NT;
            int row = idx >> 2;
            int kq = (idx & 3) << 2;
            float4 v = *reinterpret_cast<const float4*>(A + (size_t)row * ldA + k0 + kq);
            As[kq + 0][row] = v.x; As[kq + 1][row] = v.y;
            As[kq + 2][row] = v.z; As[kq + 3][row] = v.w;
        }
        // load W tile -> Ws[k][n]
        #pragma unroll
        for (int j = 0; j < (W4 + NT - 1) / NT; j++) {
            int idx = tid + j * NT;
            if (W4 % NT != 0 && idx >= W4) break;
            if (WT) {
                int row = idx >> 2;            // n
                int kq = (idx & 3) << 2;
                float4 v = *reinterpret_cast<const float4*>(W + (size_t)(n0 + row) * ldW + k0 + kq);
                Ws[kq + 0][row] = v.x; Ws[kq + 1][row] = v.y;
                Ws[kq + 2][row] = v.z; Ws[kq + 3][row] = v.w;
            } else {
                constexpr int WPR = BN / 4;
                int row = idx / WPR;           // k
                int col = (idx % WPR) << 2;    // n
                float4 v = *reinterpret_cast<const float4*>(W + (size_t)(k0 + row) * ldW + n0 + col);
                *reinterpret_cast<float4*>(&Ws[row][col]) = v;
            }
        }
        __syncthreads();
        #pragma unroll
        for (int kk = 0; kk < BK; kk++) {
            float a[TM], w[TN];
            #pragma unroll
            for (int i = 0; i < TM; i++) a[i] = As[kk][ty * TM + i];
            #pragma unroll
            for (int j = 0; j < TN; j++) w[j] = Ws[kk][tx * TN + j];
            #pragma unroll
            for (int i = 0; i < TM; i++)
                #pragma unroll
                for (int j = 0; j < TN; j++)
                    acc[i][j] = fmaf(a[i], w[j], acc[i][j]);
        }
        __syncthreads();
    }

    float bv[TN];
    #pragma unroll
    for (int j = 0; j < TN; j++)
        bv[j] = bias ? bias[(size_t)z * sBias + n0 + tx * TN + j] : 0.f;

    #pragma unroll
    for (int i = 0; i < TM; i++) {
        float4 o;
        float* op = &o.x;
        #pragma unroll
        for (int j = 0; j < TN; j++) {
            float v = acc[i][j] + bv[j];
            if (E) v += E[(size_t)(ty * TM + i) * ldE + tx * TN + j];
            if (RELU) v = fmaxf(v, 0.f);
            op[j] = v;
        }
        *reinterpret_cast<float4*>(&C[(size_t)(ty * TM + i) * ldC + tx * TN]) = o;
    }
}

// ---------------- LayerNorm over D (in-place on g_preds) ----------------
__global__ void ln_k(const float* __restrict__ g, const float* __restrict__ bb) {
    int row = blockIdx.x;            // nb*B*STEP + b*STEP + s
    int nb = row >> 10;              // /(B*STEP)=1024
    float* p = g_preds + (size_t)row * Dn;
    int tid = threadIdx.x;           // 128 threads
    float v[4];
    float s = 0.f, sq = 0.f;
    #pragma unroll
    for (int j = 0; j < 4; j++) {
        v[j] = p[tid + j * 128];
        s += v[j]; sq += v[j] * v[j];
    }
    #pragma unroll
    for (int off = 16; off > 0; off >>= 1) {
        s  += __shfl_xor_sync(0xffffffffu, s, off);
        sq += __shfl_xor_sync(0xffffffffu, sq, off);
    }
    __shared__ float rs[4], rq[4];
    if ((tid & 31) == 0) { rs[tid >> 5] = s; rq[tid >> 5] = sq; }
    __syncthreads();
    s = rs[0] + rs[1] + rs[2] + rs[3];
    sq = rq[0] + rq[1] + rq[2] + rq[3];
    float mean = s * (1.f / (float)Dn);
    float var = sq * (1.f / (float)Dn) - mean * mean;
    float rstd = rsqrtf(var + 1e-5f);
    #pragma unroll
    for (int j = 0; j < 4; j++) {
        int d = tid + j * 128;
        p[d] = (v[j] - mean) * rstd * g[nb * Dn + d] + bb[nb * Dn + d];
    }
}

// ---------------- final: sum over blocks, de-normalize ----------------
__global__ void final_k(float* __restrict__ out) {
    size_t i = (size_t)blockIdx.x * 256 + threadIdx.x;
    const size_t TOT = (size_t)Bn * STEPn * SEGn * Cn;  // 2097152
    if (i >= TOT) return;
    int b = (int)(i >> 13);   // 8192 per b
    int c = (int)(i & 31);
    const size_t S = TOT;
    float a = g_dec2[i] + g_dec2[i + S] + g_dec2[i + 2 * S] + g_dec2[i + 3 * S];
    out[i] = a * g_std[b * Cn + c] + g_mean[b * Cn + c];
}

// ---------------- host launch ----------------
extern "C" void kernel_launch(void* const* d_in, const int* in_sizes, int n_in,
                              void* d_out, int out_size) {
    const float* x_enc = (const float*)d_in[0];
    const float* mw    = (const float*)d_in[4];
    const float* ew1   = (const float*)d_in[5];
    const float* eb1   = (const float*)d_in[6];
    const float* ew2   = (const float*)d_in[7];
    const float* eb2   = (const float*)d_in[8];
    const float* wxh   = (const float*)d_in[9];
    const float* whh   = (const float*)d_in[10];
    const float* lng   = (const float*)d_in[11];
    const float* lnb   = (const float*)d_in[12];
    const float* dw1   = (const float*)d_in[13];
    const float* db1   = (const float*)d_in[14];
    const float* dw2   = (const float*)d_in[15];
    const float* db2   = (const float*)d_in[16];
    float* out = (float*)d_out;

    float *p_bas, *p_spec, *p_xi, *p_enc1, *p_enc2, *p_encx, *p_hA, *p_hB, *p_preds, *p_dec1, *p_dec2;
    cudaGetSymbolAddress((void**)&p_bas,  g_bas);
    cudaGetSymbolAddress((void**)&p_spec, g_spec);
    cudaGetSymbolAddress((void**)&p_xi,   g_xi);
    cudaGetSymbolAddress((void**)&p_enc1, g_enc1);
    cudaGetSymbolAddress((void**)&p_enc2, g_enc2);
    cudaGetSymbolAddress((void**)&p_encx, g_encx);
    cudaGetSymbolAddress((void**)&p_hA,   g_hA);
    cudaGetSymbolAddress((void**)&p_hB,   g_hB);
    cudaGetSymbolAddress((void**)&p_preds,g_preds);
    cudaGetSymbolAddress((void**)&p_dec1, g_dec1);
    cudaGetSymbolAddress((void**)&p_dec2, g_dec2);

    tables_k  <<<(Ln * K2P + 255) / 256, 256>>>(mw);
    instnorm_k<<<Bn, 256>>>(x_enc);
    dft_k     <<<Bn, 256>>>();
    spec_k    <<<NBn * Bn, 256>>>();

    // masked irfft as batched GEMM: xi[nb,b] = Bas[512,528] @ spec[nb,b][528,32]
    gemm_k<64, 32, 4, 4, false, false><<<dim3(Cn / 32, Ln / 64, NBn * Bn), 128>>>(
        p_bas, 0, K2P,
        p_spec, (size_t)K2P * Cn, Cn,
        nullptr, 0,
        nullptr, 0, 0,
        p_xi, (size_t)Ln * Cn, Cn, K2P);

    // encoder L1: relu(xi @ ew1^T + eb1)
    gemm_k<64, 64, 4, 4, true, true><<<dim3(Hn / 64, (Bn * FREQn) / 64, NBn), 256>>>(
        p_xi, (size_t)Bn * Ln * Cn, FINn,
        ew1, (size_t)Hn * FINn, FINn,
        eb1, Hn,
        nullptr, 0, 0,
        p_enc1, (size_t)Bn * FREQn * Hn, Hn, FINn);

    // encoder L2
    gemm_k<64, 64, 4, 4, false, true><<<dim3(Dn / 64, (Bn * FREQn) / 64, NBn), 256>>>(
        p_enc1, (size_t)Bn * FREQn * Hn, Hn,
        ew2, (size_t)Dn * Hn, Hn,
        eb2, Dn,
        nullptr, 0, 0,
        p_enc2, (size_t)Bn * FREQn * Dn, Dn, Hn);

    // encx = enc @ Wxh^T (hoisted out of the scan)
    gemm_k<64, 64, 4, 4, false, true><<<dim3(Dn / 64, (Bn * FREQn) / 64, NBn), 256>>>(
        p_enc2, (size_t)Bn * FREQn * Dn, Dn,
        wxh, (size_t)Dn * Dn, Dn,
        nullptr, 0,
        nullptr, 0, 0,
        p_encx, (size_t)Bn * FREQn * Dn, Dn, Dn);

    // RNN recurrence: h_t = encx_t + h_{t-1} @ Whh^T   (h_0 = encx_0)
    for (int tau = 1; tau < FREQn; tau++) {
        const float* Ap; size_t sAv; int ldAv;
        if (tau == 1) { Ap = p_encx; sAv = (size_t)Bn * FREQn * Dn; ldAv = FREQn * Dn; }
        else if (tau % 2 == 0) { Ap = p_hA; sAv = (size_t)Bn * Dn; ldAv = Dn; }
        else { Ap = p_hB; sAv = (size_t)Bn * Dn; ldAv = Dn; }
        float* Cp = (tau % 2 == 1) ? p_hA : p_hB;
        gemm_k<64, 64, 4, 4, false, true><<<dim3(Dn / 64, Bn / 64, NBn), 256>>>(
            Ap, sAv, ldAv,
            whh, (size_t)Dn * Dn, Dn,
            nullptr, 0,
            p_encx + tau * Dn, (size_t)Bn * FREQn * Dn, FREQn * Dn,
            Cp, (size_t)Bn * Dn, Dn, Dn);
    }
    // free-run: preds_s = h @ (Whh^T)^(s+1)   (final h sits in g_hA)
    for (int s = 0; s < STEPn; s++) {
        const float* Ap; size_t sAv; int ldAv;
        if (s == 0) { Ap = p_hA; sAv = (size_t)Bn * Dn; ldAv = Dn; }
        else { Ap = p_preds + (s - 1) * Dn; sAv = (size_t)Bn * STEPn * Dn; ldAv = STEPn * Dn; }
        gemm_k<64, 64, 4, 4, false, true><<<dim3(Dn / 64, Bn / 64, NBn), 256>>>(
            Ap, sAv, ldAv,
            whh, (size_t)Dn * Dn, Dn,
            nullptr, 0,
            nullptr, 0, 0,
            p_preds + s * Dn, (size_t)Bn * STEPn * Dn, STEPn * Dn, Dn);
    }

    ln_k<<<NBn * Bn * STEPn, 128>>>(lng, lnb);

    // decoder L1: relu(preds @ dw1^T + db1)
    gemm_k<64, 64, 4, 4, true, true><<<dim3(Hn / 64, (Bn * STEPn) / 64, NBn), 256>>>(
        p_preds, (size_t)Bn * STEPn * Dn, Dn,
        dw1, (size_t)Hn * Dn, Dn,
        db1, Hn,
        nullptr, 0, 0,
        p_dec1, (size_t)Bn * STEPn * Hn, Hn, Dn);

    // decoder L2
    gemm_k<64, 64, 4, 4, false, true><<<dim3(FINn / 64, (Bn * STEPn) / 64, NBn), 256>>>(
        p_dec1, (size_t)Bn * STEPn * Hn, Hn,
        dw2, (size_t)FINn * Hn, Hn,
        db2, FINn,
        nullptr, 0, 0,
        p_dec2, (size_t)Bn * STEPn * FINn, FINn, Hn);

    final_k<<<(Bn * STEPn * SEGn * Cn + 255) / 256, 256>>>(out);
}

// round 12
// speedup vs baseline: 2.5102x; 1.5545x over previous
#include <cuda_runtime.h>
#include <cuda_bf16.h>
#include <math.h>
#include <stdint.h>

// ---------------- problem dims ----------------
#define Bn   256
#define Ln   512
#define Cn   32
#define NBn  4
#define SEGn 64
#define FREQn 8
#define STEPn 4
#define Dn   512
#define Hn   1024
#define FINn 2048
#define Fn   257       // rfft bins
#define K2P  528       // 2*F=514 padded to multiple of 16

// ---------------- scratch ----------------
__device__ float g_xn   [(size_t)Bn*Ln*Cn];
__device__ float g_mean [Bn*Cn];
__device__ float g_std  [Bn*Cn];
__device__ float g_XfRe [(size_t)Bn*Fn*Cn];
__device__ float g_XfIm [(size_t)Bn*Fn*Cn];
__device__ float g_cos  [Fn*Ln];
__device__ float g_sin  [Fn*Ln];
__device__ float g_cf   [NBn*Fn];
__device__ float g_bas  [Ln*K2P];
__device__ float g_spec [(size_t)NBn*Bn*K2P*Cn];
__device__ float g_xi   [(size_t)NBn*Bn*Ln*Cn];
__device__ float g_enc1 [(size_t)NBn*Bn*FREQn*Hn];
__device__ float g_enc2 [(size_t)NBn*Bn*FREQn*Dn];
__device__ float g_encx [(size_t)NBn*Bn*FREQn*Dn];
__device__ float g_hA   [NBn*Bn*Dn];
__device__ float g_hB   [NBn*Bn*Dn];
__device__ float g_preds[NBn*Bn*STEPn*Dn];
__device__ float g_dec1 [(size_t)NBn*Bn*STEPn*Hn];
__device__ float g_dec2 [(size_t)NBn*Bn*STEPn*FINn];
// split-bf16 weights ([N,K] row-major, hi + lo)
__device__ __nv_bfloat16 g_ew1h[(size_t)NBn*Hn*FINn], g_ew1l[(size_t)NBn*Hn*FINn];
__device__ __nv_bfloat16 g_ew2h[(size_t)NBn*Dn*Hn],   g_ew2l[(size_t)NBn*Dn*Hn];
__device__ __nv_bfloat16 g_wxhh[(size_t)NBn*Dn*Dn],   g_wxhl[(size_t)NBn*Dn*Dn];
__device__ __nv_bfloat16 g_whhh[(size_t)NBn*Dn*Dn],   g_whhl[(size_t)NBn*Dn*Dn];
__device__ __nv_bfloat16 g_dw1h[(size_t)NBn*Hn*Dn],   g_dw1l[(size_t)NBn*Hn*Dn];
__device__ __nv_bfloat16 g_dw2h[(size_t)NBn*FINn*Hn], g_dw2l[(size_t)NBn*FINn*Hn];

// ---------------- tables: trig, irfft basis, sigmoid(mask) [R7 proven] ----------------
__global__ void tables_k(const float* __restrict__ mw) {
    int i = blockIdx.x * 256 + threadIdx.x;
    const float STEPA = 6.28318530717958647692f / (float)Ln;
    if (i < Fn * Ln) {
        int k = i >> 9, t = i & 511;
        int ph = (k * t) & (Ln - 1);
        float s, c;
        sincosf((float)ph * STEPA, &s, &c);
        g_cos[i] = c; g_sin[i] = s;
    }
    if (i < Ln * K2P) {
        int t = i / K2P, k2 = i % K2P;
        float v = 0.f;
        if (k2 < 2 * Fn) {
            int k = k2 >> 1;
            int ph = (k * t) & (Ln - 1);
            float ang = (float)ph * STEPA;
            float w = ((k == 0) || (k == Fn - 1)) ? 1.f : 2.f;
            w *= (1.f / (float)Ln);
            v = (k2 & 1) ? (-w * sinf(ang)) : (w * cosf(ang));
        }
        g_bas[i] = v;
    }
    if (i < NBn * Fn) g_cf[i] = 1.f / (1.f + expf(-mw[i]));
}

// ---------------- instance norm over time [R7 proven] ----------------
__global__ void instnorm_k(const float* __restrict__ x) {
    int b = blockIdx.x;
    int c = threadIdx.x & 31, r = threadIdx.x >> 5;
    const float* xb = x + (size_t)b * Ln * Cn;
    float s = 0.f, sq = 0.f;
    for (int t = r; t < Ln; t += 8) {
        float v = xb[t * Cn + c];
        s += v; sq += v * v;
    }
    __shared__ float ss[8][32], sg[8][32];
    __shared__ float smean[32], srstd[32];
    ss[r][c] = s; sg[r][c] = sq;
    __syncthreads();
    if (threadIdx.x < 32) {
        float a = 0.f, q = 0.f;
        #pragma unroll
        for (int j = 0; j < 8; j++) { a += ss[j][threadIdx.x]; q += sg[j][threadIdx.x]; }
        float m  = a * (1.f / (float)Ln);
        float var = q * (1.f / (float)Ln) - m * m;
        float sd = sqrtf(var + 1e-5f);
        g_mean[b * Cn + threadIdx.x] = m;
        g_std [b * Cn + threadIdx.x] = sd;
        smean[threadIdx.x] = m;
        srstd[threadIdx.x] = 1.f / sd;
    }
    __syncthreads();
    float m = smean[c], rs = srstd[c];
    float* xo = g_xn + (size_t)b * Ln * Cn;
    for (int t = r; t < Ln; t += 8)
        xo[t * Cn + c] = (xb[t * Cn + c] - m) * rs;
}

// ---------------- forward DFT (rfft), even/odd folded [R7 proven] ----------------
__global__ void dft_k() {
    int b = blockIdx.x;
    int warp = threadIdx.x >> 5, c = threadIdx.x & 31;
    const float* xb = g_xn + (size_t)b * Ln * Cn;
    float x0   = xb[c];
    float x256 = xb[256 * Cn + c];
    for (int k = warp; k < Fn; k += 8) {
        const float* tc = g_cos + (size_t)k * Ln;
        const float* ts = g_sin + (size_t)k * Ln;
        float re = x0 + ((k & 1) ? -x256 : x256);
        float im = 0.f;
        #pragma unroll 4
        for (int t = 1; t <= 255; t++) {
            float v1 = xb[t * Cn + c];
            float v2 = xb[(Ln - t) * Cn + c];
            re = fmaf(v1 + v2, tc[t], re);
            im = fmaf(v1 - v2, ts[t], im);
        }
        g_XfRe[((size_t)b * Fn + k) * Cn + c] = re;
        g_XfIm[((size_t)b * Fn + k) * Cn + c] = -im;
    }
}

// ---------------- scaled spectrum [R7 proven] ----------------
__global__ void spec_k() {
    int blk = blockIdx.x;
    int nb = blk >> 8, b = blk & 255;
    float* out = g_spec + (size_t)(nb * Bn + b) * K2P * Cn;
    const float* re = g_XfRe + (size_t)b * Fn * Cn;
    const float* im = g_XfIm + (size_t)b * Fn * Cn;
    for (int idx = threadIdx.x; idx < Fn * Cn; idx += blockDim.x) {
        int k = idx >> 5, c = idx & 31;
        float cf = g_cf[nb * Fn + k];
        out[(2 * k)     * Cn + c] = re[idx] * cf;
        out[(2 * k + 1) * Cn + c] = im[idx] * cf;
    }
    for (int idx = 2 * Fn * Cn + threadIdx.x; idx < K2P * Cn; idx += blockDim.x)
        out[idx] = 0.f;
}

// ---------------- fp32 tiled SGEMM [R7 proven] ----------------
template<int BM, int BN, int TM, int TN, bool RELU, bool WT>
__global__ void __launch_bounds__((BM/TM)*(BN/TN))
gemm_k(const float* __restrict__ A, size_t sA, int ldA,
       const float* __restrict__ W, size_t sW, int ldW,
       const float* __restrict__ bias, int sBias,
       const float* __restrict__ E, size_t sE, int ldE,
       float* __restrict__ C, size_t sC, int ldC,
       int K)
{
    constexpr int BK = 16;
    constexpr int NT = (BM / TM) * (BN / TN);
    constexpr int A4 = BM * BK / 4;
    constexpr int W4 = BN * BK / 4;
    __shared__ float As[BK][BM];
    __shared__ float Ws[BK][BN];

    int tid = threadIdx.x;
    int z = blockIdx.z;
    int m0 = blockIdx.y * BM, n0 = blockIdx.x * BN;

    A += z * sA + (size_t)m0 * ldA;
    W += z * sW;
    C += z * sC + (size_t)m0 * ldC + n0;
    if (E) E += z * sE + (size_t)m0 * ldE + n0;

    int tx = tid % (BN / TN), ty = tid / (BN / TN);
    float acc[TM][TN];
    #pragma unroll
    for (int i = 0; i < TM; i++)
        #pragma unroll
        for (int j = 0; j < TN; j++) acc[i][j] = 0.f;

    for (int k0 = 0; k0 < K; k0 += BK) {
        #pragma unroll
        for (int j = 0; j < A4 / NT; j++) {
            int idx = tid + j * NT;
            int row = idx >> 2;
            int kq = (idx & 3) << 2;
            float4 v = *reinterpret_cast<const float4*>(A + (size_t)row * ldA + k0 + kq);
            As[kq + 0][row] = v.x; As[kq + 1][row] = v.y;
            As[kq + 2][row] = v.z; As[kq + 3][row] = v.w;
        }
        #pragma unroll
        for (int j = 0; j < (W4 + NT - 1) / NT; j++) {
            int idx = tid + j * NT;
            if (W4 % NT != 0 && idx >= W4) break;
            if (WT) {
                int row = idx >> 2;
                int kq = (idx & 3) << 2;
                float4 v = *reinterpret_cast<const float4*>(W + (size_t)(n0 + row) * ldW + k0 + kq);
                Ws[kq + 0][row] = v.x; Ws[kq + 1][row] = v.y;
                Ws[kq + 2][row] = v.z; Ws[kq + 3][row] = v.w;
            } else {
                constexpr int WPR = BN / 4;
                int row = idx / WPR;
                int col = (idx % WPR) << 2;
                float4 v = *reinterpret_cast<const float4*>(W + (size_t)(k0 + row) * ldW + n0 + col);
                *reinterpret_cast<float4*>(&Ws[row][col]) = v;
            }
        }
        __syncthreads();
        #pragma unroll
        for (int kk = 0; kk < BK; kk++) {
            float a[TM], w[TN];
            #pragma unroll
            for (int i = 0; i < TM; i++) a[i] = As[kk][ty * TM + i];
            #pragma unroll
            for (int j = 0; j < TN; j++) w[j] = Ws[kk][tx * TN + j];
            #pragma unroll
            for (int i = 0; i < TM; i++)
                #pragma unroll
                for (int j = 0; j < TN; j++)
                    acc[i][j] = fmaf(a[i], w[j], acc[i][j]);
        }
        __syncthreads();
    }

    float bv[TN];
    #pragma unroll
    for (int j = 0; j < TN; j++)
        bv[j] = bias ? bias[(size_t)z * sBias + n0 + tx * TN + j] : 0.f;

    #pragma unroll
    for (int i = 0; i < TM; i++) {
        float4 o;
        float* op = &o.x;
        #pragma unroll
        for (int j = 0; j < TN; j++) {
            float v = acc[i][j] + bv[j];
            if (E) v += E[(size_t)(ty * TM + i) * ldE + tx * TN + j];
            if (RELU) v = fmaxf(v, 0.f);
            op[j] = v;
        }
        *reinterpret_cast<float4*>(&C[(size_t)(ty * TM + i) * ldC + tx * TN]) = o;
    }
}

// ---------------- split fp32 -> bf16 hi/lo ----------------
__global__ void split_k(const float* __restrict__ s, __nv_bfloat16* __restrict__ h,
                        __nv_bfloat16* __restrict__ l, int n) {
    int i = blockIdx.x * 256 + threadIdx.x;
    if (i >= n) return;
    float v = s[i];
    __nv_bfloat16 hh = __float2bfloat16(v);
    h[i] = hh;
    l[i] = __float2bfloat16(v - __bfloat162float(hh));
}

// ---------------- warp-MMA split-bf16 GEMM (HMMA) ----------------
#define MMA_OP(c, a0, a1, a2, a3, b0, b1) \
    asm volatile("mma.sync.aligned.m16n8k16.row.col.f32.bf16.bf16.f32 " \
        "{%0,%1,%2,%3}, {%4,%5,%6,%7}, {%8,%9}, {%0,%1,%2,%3};" \
        : "+f"((c)[0]), "+f"((c)[1]), "+f"((c)[2]), "+f"((c)[3]) \
        : "r"(a0), "r"(a1), "r"(a2), "r"(a3), "r"(b0), "r"(b1))

template<int BM, int BN, int WM, int WN, bool RELU, bool HASE>
__global__ void __launch_bounds__((BM/WM)*(BN/WN)*32, 2)
mgemm_k(const float* __restrict__ A, size_t sA, int ldA, int zAs,
        const __nv_bfloat16* __restrict__ Bh, const __nv_bfloat16* __restrict__ Bl,
        size_t sB, int ldB, int zBm,
        const float* __restrict__ bias, int sBias,
        const float* __restrict__ E, size_t sE, int ldE,
        float* __restrict__ C, size_t sC, int ldC, int K)
{
    constexpr int NWARP = (BM/WM)*(BN/WN);
    constexpr int NT = NWARP * 32;
    constexpr int PAD = 40;
    constexpr int MF = WM / 16, NF = WN / 8;

    __shared__ __nv_bfloat16 sAh[BM*PAD], sAl[BM*PAD];
    __shared__ __nv_bfloat16 sBh[BN*PAD], sBl[BN*PAD];

    int tid = threadIdx.x, warp = tid >> 5, lane = tid & 31;
    int z = blockIdx.z, m0 = blockIdx.y * BM, n0 = blockIdx.x * BN;

    A  += (size_t)(z >> zAs) * sA + (size_t)m0 * ldA;
    // FIX (R11 bug): B tile must start at global row n0
    Bh += (size_t)(z & zBm) * sB + (size_t)n0 * ldB;
    Bl += (size_t)(z & zBm) * sB + (size_t)n0 * ldB;

    int wm = warp % (BM / WM), wn = warp / (BM / WM);
    int mB = wm * WM, nB = wn * WN;

    float acc[MF][NF][4];
    #pragma unroll
    for (int i = 0; i < MF; i++)
        #pragma unroll
        for (int j = 0; j < NF; j++)
            #pragma unroll
            for (int q = 0; q < 4; q++) acc[i][j][q] = 0.f;

    for (int k0 = 0; k0 < K; k0 += 32) {
        #pragma unroll
        for (int j = 0; j < BM * 8 / NT; j++) {
            int idx = tid + j * NT;
            int row = idx >> 3, c4 = idx & 7;
            float4 v = *reinterpret_cast<const float4*>(A + (size_t)row * ldA + k0 + c4 * 4);
            union { __nv_bfloat162 b; uint32_t u; } h0, h1, l0, l1;
            h0.b = __float22bfloat162_rn(make_float2(v.x, v.y));
            h1.b = __float22bfloat162_rn(make_float2(v.z, v.w));
            float2 r0 = __bfloat1622float2(h0.b), r1 = __bfloat1622float2(h1.b);
            l0.b = __float22bfloat162_rn(make_float2(v.x - r0.x, v.y - r0.y));
            l1.b = __float22bfloat162_rn(make_float2(v.z - r1.x, v.w - r1.y));
            *reinterpret_cast<uint2*>(&sAh[row * PAD + c4 * 4]) = make_uint2(h0.u, h1.u);
            *reinterpret_cast<uint2*>(&sAl[row * PAD + c4 * 4]) = make_uint2(l0.u, l1.u);
        }
        #pragma unroll
        for (int j = 0; j < BN * 4 / NT; j++) {
            int idx = tid + j * NT;
            int row = idx >> 2, c8 = idx & 3;
            *reinterpret_cast<uint4*>(&sBh[row * PAD + c8 * 8]) =
                *reinterpret_cast<const uint4*>(Bh + (size_t)row * ldB + k0 + c8 * 8);
            *reinterpret_cast<uint4*>(&sBl[row * PAD + c8 * 8]) =
                *reinterpret_cast<const uint4*>(Bl + (size_t)row * ldB + k0 + c8 * 8);
        }
        __syncthreads();

        #pragma unroll
        for (int ks = 0; ks < 32; ks += 16) {
            int kk = ks + (lane & 3) * 2;
            int r0 = mB + (lane >> 2);
            uint32_t ah[MF][4], al[MF][4];
            #pragma unroll
            for (int mf = 0; mf < MF; mf++) {
                int r = r0 + mf * 16;
                ah[mf][0] = *reinterpret_cast<const uint32_t*>(&sAh[r * PAD + kk]);
                ah[mf][1] = *reinterpret_cast<const uint32_t*>(&sAh[(r + 8) * PAD + kk]);
                ah[mf][2] = *reinterpret_cast<const uint32_t*>(&sAh[r * PAD + kk + 8]);
                ah[mf][3] = *reinterpret_cast<const uint32_t*>(&sAh[(r + 8) * PAD + kk + 8]);
                al[mf][0] = *reinterpret_cast<const uint32_t*>(&sAl[r * PAD + kk]);
                al[mf][1] = *reinterpret_cast<const uint32_t*>(&sAl[(r + 8) * PAD + kk]);
                al[mf][2] = *reinterpret_cast<const uint32_t*>(&sAl[r * PAD + kk + 8]);
                al[mf][3] = *reinterpret_cast<const uint32_t*>(&sAl[(r + 8) * PAD + kk + 8]);
            }
            #pragma unroll
            for (int nf = 0; nf < NF; nf++) {
                int cB = nB + nf * 8 + (lane >> 2);
                uint32_t bh0 = *reinterpret_cast<const uint32_t*>(&sBh[cB * PAD + kk]);
                uint32_t bh1 = *reinterpret_cast<const uint32_t*>(&sBh[cB * PAD + kk + 8]);
                uint32_t bl0 = *reinterpret_cast<const uint32_t*>(&sBl[cB * PAD + kk]);
                uint32_t bl1 = *reinterpret_cast<const uint32_t*>(&sBl[cB * PAD + kk + 8]);
                #pragma unroll
                for (int mf = 0; mf < MF; mf++) {
                    MMA_OP(acc[mf][nf], ah[mf][0], ah[mf][1], ah[mf][2], ah[mf][3], bh0, bh1);
                    MMA_OP(acc[mf][nf], al[mf][0], al[mf][1], al[mf][2], al[mf][3], bh0, bh1);
                    MMA_OP(acc[mf][nf], ah[mf][0], ah[mf][1], ah[mf][2], ah[mf][3], bl0, bl1);
                }
            }
        }
        __syncthreads();
    }

    C += (size_t)z * sC + (size_t)m0 * ldC + n0;
    if (HASE) E += (size_t)z * sE + (size_t)m0 * ldE + n0;
    #pragma unroll
    for (int mf = 0; mf < MF; mf++) {
        #pragma unroll
        for (int nf = 0; nf < NF; nf++) {
            int r = mB + mf * 16 + (lane >> 2);
            int cc = nB + nf * 8 + (lane & 3) * 2;
            float b0 = 0.f, b1 = 0.f;
            if (bias) {
                b0 = bias[(size_t)z * sBias + n0 + cc];
                b1 = bias[(size_t)z * sBias + n0 + cc + 1];
            }
            float v0 = acc[mf][nf][0] + b0, v1 = acc[mf][nf][1] + b1;
            float v2 = acc[mf][nf][2] + b0, v3 = acc[mf][nf][3] + b1;
            if (HASE) {
                v0 += E[(size_t)r * ldE + cc];       v1 += E[(size_t)r * ldE + cc + 1];
                v2 += E[(size_t)(r + 8) * ldE + cc]; v3 += E[(size_t)(r + 8) * ldE + cc + 1];
            }
            if (RELU) {
                v0 = fmaxf(v0, 0.f); v1 = fmaxf(v1, 0.f);
                v2 = fmaxf(v2, 0.f); v3 = fmaxf(v3, 0.f);
            }
            *reinterpret_cast<float2*>(&C[(size_t)r * ldC + cc]) = make_float2(v0, v1);
            *reinterpret_cast<float2*>(&C[(size_t)(r + 8) * ldC + cc]) = make_float2(v2, v3);
        }
    }
}

// ---------------- LayerNorm over D [R7 proven] ----------------
__global__ void ln_k(const float* __restrict__ g, const float* __restrict__ bb) {
    int row = blockIdx.x;
    int nb = row >> 10;
    float* p = g_preds + (size_t)row * Dn;
    int tid = threadIdx.x;
    float v[4];
    float s = 0.f, sq = 0.f;
    #pragma unroll
    for (int j = 0; j < 4; j++) { v[j] = p[tid + j*128]; s += v[j]; sq += v[j]*v[j]; }
    #pragma unroll
    for (int off = 16; off > 0; off >>= 1) {
        s  += __shfl_xor_sync(0xffffffffu, s, off);
        sq += __shfl_xor_sync(0xffffffffu, sq, off);
    }
    __shared__ float rs[4], rq[4];
    if ((tid & 31) == 0) { rs[tid>>5] = s; rq[tid>>5] = sq; }
    __syncthreads();
    s = rs[0]+rs[1]+rs[2]+rs[3];
    sq = rq[0]+rq[1]+rq[2]+rq[3];
    float mean = s * (1.f/512.f);
    float var = sq * (1.f/512.f) - mean*mean;
    float rstd = rsqrtf(var + 1e-5f);
    #pragma unroll
    for (int j = 0; j < 4; j++) {
        int d = tid + j*128;
        p[d] = (v[j]-mean)*rstd*g[nb*Dn+d] + bb[nb*Dn+d];
    }
}

// ---------------- final: sum blocks, de-normalize [R7 proven] ----------------
__global__ void final_k(float* __restrict__ out) {
    size_t i = (size_t)blockIdx.x * 256 + threadIdx.x;
    const size_t TOT = (size_t)Bn * STEPn * SEGn * Cn;
    if (i >= TOT) return;
    int b = (int)(i >> 13);
    int c = (int)(i & 31);
    float a = g_dec2[i] + g_dec2[i+TOT] + g_dec2[i+2*TOT] + g_dec2[i+3*TOT];
    out[i] = a * g_std[b*Cn+c] + g_mean[b*Cn+c];
}

// ---------------- host ----------------
static inline float* sym(const void* s) { void* p; cudaGetSymbolAddress(&p, s); return (float*)p; }

extern "C" void kernel_launch(void* const* d_in, const int* in_sizes, int n_in,
                              void* d_out, int out_size) {
    const float* x_enc = (const float*)d_in[0];
    const float* mw  = (const float*)d_in[4];
    const float* ew1 = (const float*)d_in[5];
    const float* eb1 = (const float*)d_in[6];
    const float* ew2 = (const float*)d_in[7];
    const float* eb2 = (const float*)d_in[8];
    const float* wxh = (const float*)d_in[9];
    const float* whh = (const float*)d_in[10];
    const float* lng = (const float*)d_in[11];
    const float* lnb = (const float*)d_in[12];
    const float* dw1 = (const float*)d_in[13];
    const float* db1 = (const float*)d_in[14];
    const float* dw2 = (const float*)d_in[15];
    const float* db2 = (const float*)d_in[16];
    float* out = (float*)d_out;

    float* p_bas  = sym(g_bas);
    float* p_spec = sym(g_spec);
    float* p_xi   = sym(g_xi);
    float* p_enc1 = sym(g_enc1);
    float* p_enc2 = sym(g_enc2);
    float* p_encx = sym(g_encx);
    float* p_hA   = sym(g_hA);
    float* p_hB   = sym(g_hB);
    float* p_preds= sym(g_preds);
    float* p_dec1 = sym(g_dec1);
    float* p_dec2 = sym(g_dec2);
    __nv_bfloat16* p_ew1h = (__nv_bfloat16*)sym(g_ew1h);
    __nv_bfloat16* p_ew1l = (__nv_bfloat16*)sym(g_ew1l);
    __nv_bfloat16* p_ew2h = (__nv_bfloat16*)sym(g_ew2h);
    __nv_bfloat16* p_ew2l = (__nv_bfloat16*)sym(g_ew2l);
    __nv_bfloat16* p_wxhh = (__nv_bfloat16*)sym(g_wxhh);
    __nv_bfloat16* p_wxhl = (__nv_bfloat16*)sym(g_wxhl);
    __nv_bfloat16* p_whhh = (__nv_bfloat16*)sym(g_whhh);
    __nv_bfloat16* p_whhl = (__nv_bfloat16*)sym(g_whhl);
    __nv_bfloat16* p_dw1h = (__nv_bfloat16*)sym(g_dw1h);
    __nv_bfloat16* p_dw1l = (__nv_bfloat16*)sym(g_dw1l);
    __nv_bfloat16* p_dw2h = (__nv_bfloat16*)sym(g_dw2h);
    __nv_bfloat16* p_dw2l = (__nv_bfloat16*)sym(g_dw2l);

    // ---- proven R7 front-end ----
    tables_k  <<<(Ln * K2P + 255) / 256, 256>>>(mw);
    instnorm_k<<<Bn, 256>>>(x_enc);
    dft_k     <<<Bn, 256>>>();
    spec_k    <<<NBn * Bn, 256>>>();

    // masked irfft as batched fp32 GEMM: xi[nb,b] = Bas[512,528] @ spec[nb,b][528,32]
    gemm_k<64, 32, 4, 4, false, false><<<dim3(Cn / 32, Ln / 64, NBn * Bn), 128>>>(
        p_bas, 0, K2P,
        p_spec, (size_t)K2P * Cn, Cn,
        nullptr, 0,
        nullptr, 0, 0,
        p_xi, (size_t)Ln * Cn, Cn, K2P);

    // ---- split weights ----
    split_k<<<(NBn*Hn*FINn+255)/256,256>>>(ew1, p_ew1h, p_ew1l, NBn*Hn*FINn);
    split_k<<<(NBn*Dn*Hn +255)/256,256>>>(ew2, p_ew2h, p_ew2l, NBn*Dn*Hn);
    split_k<<<(NBn*Dn*Dn +255)/256,256>>>(wxh, p_wxhh, p_wxhl, NBn*Dn*Dn);
    split_k<<<(NBn*Dn*Dn +255)/256,256>>>(whh, p_whhh, p_whhl, NBn*Dn*Dn);
    split_k<<<(NBn*Hn*Dn +255)/256,256>>>(dw1, p_dw1h, p_dw1l, NBn*Hn*Dn);
    split_k<<<(NBn*FINn*Hn+255)/256,256>>>(dw2, p_dw2h, p_dw2l, NBn*FINn*Hn);

    // ---- HMMA weight GEMMs ----
    // enc L1: relu(xi @ ew1^T + eb1)
    mgemm_k<128,128,64,32,true,false><<<dim3(Hn/128, 16, NBn), 256>>>(
        p_xi, (size_t)Bn*Ln*Cn, FINn, 0,
        p_ew1h, p_ew1l, (size_t)Hn*FINn, FINn, 0x7fffffff,
        eb1, Hn, nullptr, 0, 0,
        p_enc1, (size_t)Bn*FREQn*Hn, Hn, FINn);

    // enc L2
    mgemm_k<128,128,64,32,false,false><<<dim3(Dn/128, 16, NBn), 256>>>(
        p_enc1, (size_t)Bn*FREQn*Hn, Hn, 0,
        p_ew2h, p_ew2l, (size_t)Dn*Hn, Hn, 0x7fffffff,
        eb2, Dn, nullptr, 0, 0,
        p_enc2, (size_t)Bn*FREQn*Dn, Dn, Hn);

    // encx = enc @ Wxh^T
    mgemm_k<128,128,64,32,false,false><<<dim3(Dn/128, 16, NBn), 256>>>(
        p_enc2, (size_t)Bn*FREQn*Dn, Dn, 0,
        p_wxhh, p_wxhl, (size_t)Dn*Dn, Dn, 0x7fffffff,
        nullptr, 0, nullptr, 0, 0,
        p_encx, (size_t)Bn*FREQn*Dn, Dn, Dn);

    // RNN: h_t = encx_t + h_{t-1} @ Whh^T
    for (int tau = 1; tau < FREQn; tau++) {
        const float* Ap; size_t sAv; int ldAv;
        if (tau == 1) { Ap = p_encx; sAv = (size_t)Bn*FREQn*Dn; ldAv = FREQn*Dn; }
        else if (tau % 2 == 0) { Ap = p_hA; sAv = (size_t)Bn*Dn; ldAv = Dn; }
        else { Ap = p_hB; sAv = (size_t)Bn*Dn; ldAv = Dn; }
        float* Cp = (tau % 2 == 1) ? p_hA : p_hB;
        mgemm_k<128,128,64,32,false,true><<<dim3(Dn/128, 2, NBn), 256>>>(
            Ap, sAv, ldAv, 0,
            p_whhh, p_whhl, (size_t)Dn*Dn, Dn, 0x7fffffff,
            nullptr, 0,
            p_encx + tau*Dn, (size_t)Bn*FREQn*Dn, FREQn*Dn,
            Cp, (size_t)Bn*Dn, Dn, Dn);
    }
    // free-run: preds_s = h @ Whh^T (chained)
    for (int s = 0; s < STEPn; s++) {
        const float* Ap; size_t sAv; int ldAv;
        if (s == 0) { Ap = p_hA; sAv = (size_t)Bn*Dn; ldAv = Dn; }
        else { Ap = p_preds + (s-1)*Dn; sAv = (size_t)Bn*STEPn*Dn; ldAv = STEPn*Dn; }
        mgemm_k<128,128,64,32,false,false><<<dim3(Dn/128, 2, NBn), 256>>>(
            Ap, sAv, ldAv, 0,
            p_whhh, p_whhl, (size_t)Dn*Dn, Dn, 0x7fffffff,
            nullptr, 0, nullptr, 0, 0,
            p_preds + s*Dn, (size_t)Bn*STEPn*Dn, STEPn*Dn, Dn);
    }

    ln_k<<<NBn*Bn*STEPn, 128>>>(lng, lnb);

    // dec L1: relu(preds @ dw1^T + db1)
    mgemm_k<128,128,64,32,true,false><<<dim3(Hn/128, 8, NBn), 256>>>(
        p_preds, (size_t)Bn*STEPn*Dn, Dn, 0,
        p_dw1h, p_dw1l, (size_t)Hn*Dn, Dn, 0x7fffffff,
        db1, Hn, nullptr, 0, 0,
        p_dec1, (size_t)Bn*STEPn*Hn, Hn, Dn);

    // dec L2
    mgemm_k<128,128,64,32,false,false><<<dim3(FINn/128, 8, NBn), 256>>>(
        p_dec1, (size_t)Bn*STEPn*Hn, Hn, 0,
        p_dw2h, p_dw2l, (size_t)FINn*Hn, Hn, 0x7fffffff,
        db2, FINn, nullptr, 0, 0,
        p_dec2, (size_t)Bn*STEPn*FINn, FINn, Hn);

    final_k<<<(Bn*STEPn*SEGn*Cn+255)/256, 256>>>(out);
}

// round 13
// speedup vs baseline: 3.7092x; 1.4777x over previous
#include <cuda_runtime.h>
#include <cuda_bf16.h>
#include <math.h>
#include <stdint.h>

// ---------------- problem dims ----------------
#define Bn   256
#define Ln   512
#define Cn   32
#define NBn  4
#define SEGn 64
#define FREQn 8
#define STEPn 4
#define Dn   512
#define Hn   1024
#define FINn 2048
#define Fn   257

// ---------------- scratch ----------------
__device__ float g_mean [Bn*Cn];
__device__ float g_std  [Bn*Cn];
__device__ float g_cf   [NBn*Fn];
__device__ float g_rho  [NBn*Ln];
__device__ float g_T    [(size_t)NBn*Ln*Ln];
__device__ __nv_bfloat16 g_xnTh[(size_t)Bn*Cn*Ln], g_xnTl[(size_t)Bn*Cn*Ln];
__device__ float g_xi   [(size_t)NBn*Bn*Ln*Cn];
__device__ float g_enc1 [(size_t)NBn*Bn*FREQn*Hn];
__device__ float g_enc2 [(size_t)NBn*Bn*FREQn*Dn];
__device__ float g_encx [(size_t)NBn*Bn*FREQn*Dn];
__device__ float g_hA   [NBn*Bn*Dn];
__device__ float g_hB   [NBn*Bn*Dn];
__device__ float g_preds[NBn*Bn*STEPn*Dn];
__device__ float g_dec1 [(size_t)NBn*Bn*STEPn*Hn];
__device__ float g_dec2 [(size_t)NBn*Bn*STEPn*FINn];
// split-bf16 weights ([N,K] row-major, hi + lo)
__device__ __nv_bfloat16 g_ew1h[(size_t)NBn*Hn*FINn], g_ew1l[(size_t)NBn*Hn*FINn];
__device__ __nv_bfloat16 g_ew2h[(size_t)NBn*Dn*Hn],   g_ew2l[(size_t)NBn*Dn*Hn];
__device__ __nv_bfloat16 g_wxhh[(size_t)NBn*Dn*Dn],   g_wxhl[(size_t)NBn*Dn*Dn];
__device__ __nv_bfloat16 g_whhh[(size_t)NBn*Dn*Dn],   g_whhl[(size_t)NBn*Dn*Dn];
__device__ __nv_bfloat16 g_dw1h[(size_t)NBn*Hn*Dn],   g_dw1l[(size_t)NBn*Hn*Dn];
__device__ __nv_bfloat16 g_dw2h[(size_t)NBn*FINn*Hn], g_dw2l[(size_t)NBn*FINn*Hn];

// ---------------- prep: sigmoid(mask), circulant kernel rho, T build ----------------
__global__ void cf_k(const float* __restrict__ mw) {
    int i = blockIdx.x * 256 + threadIdx.x;
    if (i < NBn * Fn) g_cf[i] = 1.f / (1.f + expf(-mw[i]));
}
// rho[nb][d] = (cf0 + cf256*(-1)^d + 2*sum_{k=1..255} cf_k cos(2*pi*k*d/512)) / 512
__global__ void rho_k() {
    int nb = blockIdx.x, d = threadIdx.x;
    const float* cf = g_cf + nb * Fn;
    const float ST = 6.28318530717958647692f / 512.f;
    float s = cf[0] + ((d & 1) ? -cf[256] : cf[256]);
    for (int k = 1; k <= 255; k++)
        s += 2.f * cf[k] * cosf((float)((k * d) & 511) * ST);
    g_rho[nb * Ln + d] = s * (1.f / 512.f);
}
__global__ void tbuild_k() {
    int i = blockIdx.x * 256 + threadIdx.x;   // 4*512*512
    int nb = i >> 18, t = (i >> 9) & 511, tp = i & 511;
    g_T[i] = g_rho[nb * Ln + ((t - tp) & 511)];
}

// ---------------- split fp32 -> bf16 hi/lo ----------------
__global__ void split_k(const float* __restrict__ s, __nv_bfloat16* __restrict__ h,
                        __nv_bfloat16* __restrict__ l, int n) {
    int i = blockIdx.x * 256 + threadIdx.x;
    if (i >= n) return;
    float v = s[i];
    __nv_bfloat16 hh = __float2bfloat16(v);
    h[i] = hh;
    l[i] = __float2bfloat16(v - __bfloat162float(hh));
}

// ---------------- instance norm + transposed split-bf16 write ----------------
__global__ void instnorm_k(const float* __restrict__ x) {
    int b = blockIdx.x;
    int c = threadIdx.x & 31, r = threadIdx.x >> 5;
    const float* xb = x + (size_t)b * Ln * Cn;
    float s = 0.f, sq = 0.f;
    for (int t = r; t < Ln; t += 8) { float v = xb[t * Cn + c]; s += v; sq += v * v; }
    __shared__ float ss[8][32], sg[8][32], smean[32], srstd[32];
    ss[r][c] = s; sg[r][c] = sq;
    __syncthreads();
    if (threadIdx.x < 32) {
        float a = 0.f, q = 0.f;
        #pragma unroll
        for (int j = 0; j < 8; j++) { a += ss[j][threadIdx.x]; q += sg[j][threadIdx.x]; }
        float m = a * (1.f / 512.f);
        float var = q * (1.f / 512.f) - m * m;
        float sd = sqrtf(var + 1e-5f);
        g_mean[b * Cn + threadIdx.x] = m;
        g_std [b * Cn + threadIdx.x] = sd;
        smean[threadIdx.x] = m; srstd[threadIdx.x] = 1.f / sd;
    }
    __syncthreads();
    __shared__ float tile[256][33];
    for (int t0 = 0; t0 < Ln; t0 += 256) {
        for (int idx = threadIdx.x; idx < 256 * 32; idx += 256) {
            int t = idx >> 5, cc = idx & 31;
            tile[t][cc] = (xb[(t0 + t) * Cn + cc] - smean[cc]) * srstd[cc];
        }
        __syncthreads();
        for (int idx = threadIdx.x; idx < 32 * 256; idx += 256) {
            int cc = idx >> 8, t = idx & 255;
            float v = tile[t][cc];
            __nv_bfloat16 h = __float2bfloat16(v);
            size_t o = (size_t)b * Cn * Ln + (size_t)cc * Ln + t0 + t;
            g_xnTh[o] = h;
            g_xnTl[o] = __float2bfloat16(v - __bfloat162float(h));
        }
        __syncthreads();
    }
}

// ---------------- warp-MMA split-bf16 GEMM (HMMA, validated R12) ----------------
#define MMA_OP(c, a0, a1, a2, a3, b0, b1) \
    asm volatile("mma.sync.aligned.m16n8k16.row.col.f32.bf16.bf16.f32 " \
        "{%0,%1,%2,%3}, {%4,%5,%6,%7}, {%8,%9}, {%0,%1,%2,%3};" \
        : "+f"((c)[0]), "+f"((c)[1]), "+f"((c)[2]), "+f"((c)[3]) \
        : "r"(a0), "r"(a1), "r"(a2), "r"(a3), "r"(b0), "r"(b1))

template<int BM, int BN, int WM, int WN, bool RELU, bool HASE>
__global__ void __launch_bounds__((BM/WM)*(BN/WN)*32, 2)
mgemm_k(const float* __restrict__ A, size_t sA, int ldA, int zAs,
        const __nv_bfloat16* __restrict__ Bh, const __nv_bfloat16* __restrict__ Bl,
        size_t sB, int ldB, int zBm,
        const float* __restrict__ bias, int sBias,
        const float* __restrict__ E, size_t sE, int ldE,
        float* __restrict__ C, size_t sC, int ldC, int K)
{
    constexpr int NWARP = (BM/WM)*(BN/WN);
    constexpr int NT = NWARP * 32;
    constexpr int PAD = 40;
    constexpr int MF = WM / 16, NF = WN / 8;

    __shared__ __nv_bfloat16 sAh[BM*PAD], sAl[BM*PAD];
    __shared__ __nv_bfloat16 sBh[BN*PAD], sBl[BN*PAD];

    int tid = threadIdx.x, warp = tid >> 5, lane = tid & 31;
    int z = blockIdx.z, m0 = blockIdx.y * BM, n0 = blockIdx.x * BN;

    A  += (size_t)(z >> zAs) * sA + (size_t)m0 * ldA;
    Bh += (size_t)(z & zBm) * sB + (size_t)n0 * ldB;
    Bl += (size_t)(z & zBm) * sB + (size_t)n0 * ldB;

    int wm = warp % (BM / WM), wn = warp / (BM / WM);
    int mB = wm * WM, nB = wn * WN;

    float acc[MF][NF][4];
    #pragma unroll
    for (int i = 0; i < MF; i++)
        #pragma unroll
        for (int j = 0; j < NF; j++)
            #pragma unroll
            for (int q = 0; q < 4; q++) acc[i][j][q] = 0.f;

    for (int k0 = 0; k0 < K; k0 += 32) {
        #pragma unroll
        for (int j = 0; j < BM * 8 / NT; j++) {
            int idx = tid + j * NT;
            int row = idx >> 3, c4 = idx & 7;
            float4 v = *reinterpret_cast<const float4*>(A + (size_t)row * ldA + k0 + c4 * 4);
            union { __nv_bfloat162 b; uint32_t u; } h0, h1, l0, l1;
            h0.b = __float22bfloat162_rn(make_float2(v.x, v.y));
            h1.b = __float22bfloat162_rn(make_float2(v.z, v.w));
            float2 r0 = __bfloat1622float2(h0.b), r1 = __bfloat1622float2(h1.b);
            l0.b = __float22bfloat162_rn(make_float2(v.x - r0.x, v.y - r0.y));
            l1.b = __float22bfloat162_rn(make_float2(v.z - r1.x, v.w - r1.y));
            *reinterpret_cast<uint2*>(&sAh[row * PAD + c4 * 4]) = make_uint2(h0.u, h1.u);
            *reinterpret_cast<uint2*>(&sAl[row * PAD + c4 * 4]) = make_uint2(l0.u, l1.u);
        }
        #pragma unroll
        for (int j = 0; j < BN * 4 / NT; j++) {
            int idx = tid + j * NT;
            int row = idx >> 2, c8 = idx & 3;
            *reinterpret_cast<uint4*>(&sBh[row * PAD + c8 * 8]) =
                *reinterpret_cast<const uint4*>(Bh + (size_t)row * ldB + k0 + c8 * 8);
            *reinterpret_cast<uint4*>(&sBl[row * PAD + c8 * 8]) =
                *reinterpret_cast<const uint4*>(Bl + (size_t)row * ldB + k0 + c8 * 8);
        }
        __syncthreads();

        #pragma unroll
        for (int ks = 0; ks < 32; ks += 16) {
            int kk = ks + (lane & 3) * 2;
            int r0 = mB + (lane >> 2);
            uint32_t ah[MF][4], al[MF][4];
            #pragma unroll
            for (int mf = 0; mf < MF; mf++) {
                int r = r0 + mf * 16;
                ah[mf][0] = *reinterpret_cast<const uint32_t*>(&sAh[r * PAD + kk]);
                ah[mf][1] = *reinterpret_cast<const uint32_t*>(&sAh[(r + 8) * PAD + kk]);
                ah[mf][2] = *reinterpret_cast<const uint32_t*>(&sAh[r * PAD + kk + 8]);
                ah[mf][3] = *reinterpret_cast<const uint32_t*>(&sAh[(r + 8) * PAD + kk + 8]);
                al[mf][0] = *reinterpret_cast<const uint32_t*>(&sAl[r * PAD + kk]);
                al[mf][1] = *reinterpret_cast<const uint32_t*>(&sAl[(r + 8) * PAD + kk]);
                al[mf][2] = *reinterpret_cast<const uint32_t*>(&sAl[r * PAD + kk + 8]);
                al[mf][3] = *reinterpret_cast<const uint32_t*>(&sAl[(r + 8) * PAD + kk + 8]);
            }
            #pragma unroll
            for (int nf = 0; nf < NF; nf++) {
                int cB = nB + nf * 8 + (lane >> 2);
                uint32_t bh0 = *reinterpret_cast<const uint32_t*>(&sBh[cB * PAD + kk]);
                uint32_t bh1 = *reinterpret_cast<const uint32_t*>(&sBh[cB * PAD + kk + 8]);
                uint32_t bl0 = *reinterpret_cast<const uint32_t*>(&sBl[cB * PAD + kk]);
                uint32_t bl1 = *reinterpret_cast<const uint32_t*>(&sBl[cB * PAD + kk + 8]);
                #pragma unroll
                for (int mf = 0; mf < MF; mf++) {
                    MMA_OP(acc[mf][nf], ah[mf][0], ah[mf][1], ah[mf][2], ah[mf][3], bh0, bh1);
                    MMA_OP(acc[mf][nf], al[mf][0], al[mf][1], al[mf][2], al[mf][3], bh0, bh1);
                    MMA_OP(acc[mf][nf], ah[mf][0], ah[mf][1], ah[mf][2], ah[mf][3], bl0, bl1);
                }
            }
        }
        __syncthreads();
    }

    C += (size_t)z * sC + (size_t)m0 * ldC + n0;
    if (HASE) E += (size_t)z * sE + (size_t)m0 * ldE + n0;
    #pragma unroll
    for (int mf = 0; mf < MF; mf++) {
        #pragma unroll
        for (int nf = 0; nf < NF; nf++) {
            int r = mB + mf * 16 + (lane >> 2);
            int cc = nB + nf * 8 + (lane & 3) * 2;
            float b0 = 0.f, b1 = 0.f;
            if (bias) {
                b0 = bias[(size_t)z * sBias + n0 + cc];
                b1 = bias[(size_t)z * sBias + n0 + cc + 1];
            }
            float v0 = acc[mf][nf][0] + b0, v1 = acc[mf][nf][1] + b1;
            float v2 = acc[mf][nf][2] + b0, v3 = acc[mf][nf][3] + b1;
            if (HASE) {
                v0 += E[(size_t)r * ldE + cc];       v1 += E[(size_t)r * ldE + cc + 1];
                v2 += E[(size_t)(r + 8) * ldE + cc]; v3 += E[(size_t)(r + 8) * ldE + cc + 1];
            }
            if (RELU) {
                v0 = fmaxf(v0, 0.f); v1 = fmaxf(v1, 0.f);
                v2 = fmaxf(v2, 0.f); v3 = fmaxf(v3, 0.f);
            }
            *reinterpret_cast<float2*>(&C[(size_t)r * ldC + cc]) = make_float2(v0, v1);
            *reinterpret_cast<float2*>(&C[(size_t)(r + 8) * ldC + cc]) = make_float2(v2, v3);
        }
    }
}

// ---------------- LayerNorm over D ----------------
__global__ void ln_k(const float* __restrict__ g, const float* __restrict__ bb) {
    int row = blockIdx.x;
    int nb = row >> 10;
    float* p = g_preds + (size_t)row * Dn;
    int tid = threadIdx.x;
    float v[4];
    float s = 0.f, sq = 0.f;
    #pragma unroll
    for (int j = 0; j < 4; j++) { v[j] = p[tid + j*128]; s += v[j]; sq += v[j]*v[j]; }
    #pragma unroll
    for (int off = 16; off > 0; off >>= 1) {
        s  += __shfl_xor_sync(0xffffffffu, s, off);
        sq += __shfl_xor_sync(0xffffffffu, sq, off);
    }
    __shared__ float rs[4], rq[4];
    if ((tid & 31) == 0) { rs[tid>>5] = s; rq[tid>>5] = sq; }
    __syncthreads();
    s = rs[0]+rs[1]+rs[2]+rs[3];
    sq = rq[0]+rq[1]+rq[2]+rq[3];
    float mean = s * (1.f/512.f);
    float var = sq * (1.f/512.f) - mean*mean;
    float rstd = rsqrtf(var + 1e-5f);
    #pragma unroll
    for (int j = 0; j < 4; j++) {
        int d = tid + j*128;
        p[d] = (v[j]-mean)*rstd*g[nb*Dn+d] + bb[nb*Dn+d];
    }
}

// ---------------- final: sum blocks, de-normalize ----------------
__global__ void final_k(float* __restrict__ out) {
    size_t i = (size_t)blockIdx.x * 256 + threadIdx.x;
    const size_t TOT = (size_t)Bn * STEPn * SEGn * Cn;
    if (i >= TOT) return;
    int b = (int)(i >> 13);
    int c = (int)(i & 31);
    float a = g_dec2[i] + g_dec2[i+TOT] + g_dec2[i+2*TOT] + g_dec2[i+3*TOT];
    out[i] = a * g_std[b*Cn+c] + g_mean[b*Cn+c];
}

// ---------------- host ----------------
static inline float* sym(const void* s) { void* p; cudaGetSymbolAddress(&p, s); return (float*)p; }

extern "C" void kernel_launch(void* const* d_in, const int* in_sizes, int n_in,
                              void* d_out, int out_size) {
    const float* x_enc = (const float*)d_in[0];
    const float* mw  = (const float*)d_in[4];
    const float* ew1 = (const float*)d_in[5];
    const float* eb1 = (const float*)d_in[6];
    const float* ew2 = (const float*)d_in[7];
    const float* eb2 = (const float*)d_in[8];
    const float* wxh = (const float*)d_in[9];
    const float* whh = (const float*)d_in[10];
    const float* lng = (const float*)d_in[11];
    const float* lnb = (const float*)d_in[12];
    const float* dw1 = (const float*)d_in[13];
    const float* db1 = (const float*)d_in[14];
    const float* dw2 = (const float*)d_in[15];
    const float* db2 = (const float*)d_in[16];
    float* out = (float*)d_out;

    float* p_T    = sym(g_T);
    float* p_xi   = sym(g_xi);
    float* p_enc1 = sym(g_enc1);
    float* p_enc2 = sym(g_enc2);
    float* p_encx = sym(g_encx);
    float* p_hA   = sym(g_hA);
    float* p_hB   = sym(g_hB);
    float* p_preds= sym(g_preds);
    float* p_dec1 = sym(g_dec1);
    float* p_dec2 = sym(g_dec2);
    __nv_bfloat16* p_xnTh = (__nv_bfloat16*)sym(g_xnTh);
    __nv_bfloat16* p_xnTl = (__nv_bfloat16*)sym(g_xnTl);
    __nv_bfloat16* p_ew1h = (__nv_bfloat16*)sym(g_ew1h);
    __nv_bfloat16* p_ew1l = (__nv_bfloat16*)sym(g_ew1l);
    __nv_bfloat16* p_ew2h = (__nv_bfloat16*)sym(g_ew2h);
    __nv_bfloat16* p_ew2l = (__nv_bfloat16*)sym(g_ew2l);
    __nv_bfloat16* p_wxhh = (__nv_bfloat16*)sym(g_wxhh);
    __nv_bfloat16* p_wxhl = (__nv_bfloat16*)sym(g_wxhl);
    __nv_bfloat16* p_whhh = (__nv_bfloat16*)sym(g_whhh);
    __nv_bfloat16* p_whhl = (__nv_bfloat16*)sym(g_whhl);
    __nv_bfloat16* p_dw1h = (__nv_bfloat16*)sym(g_dw1h);
    __nv_bfloat16* p_dw1l = (__nv_bfloat16*)sym(g_dw1l);
    __nv_bfloat16* p_dw2h = (__nv_bfloat16*)sym(g_dw2h);
    __nv_bfloat16* p_dw2l = (__nv_bfloat16*)sym(g_dw2l);

    // ---- circulant front-end (validated via R10/R11 equality) ----
    cf_k    <<<5, 256>>>(mw);
    rho_k   <<<NBn, 512>>>();
    tbuild_k<<<4096, 256>>>();
    instnorm_k<<<Bn, 256>>>(x_enc);

    // ---- split weights ----
    split_k<<<(NBn*Hn*FINn+255)/256,256>>>(ew1, p_ew1h, p_ew1l, NBn*Hn*FINn);
    split_k<<<(NBn*Dn*Hn +255)/256,256>>>(ew2, p_ew2h, p_ew2l, NBn*Dn*Hn);
    split_k<<<(NBn*Dn*Dn +255)/256,256>>>(wxh, p_wxhh, p_wxhl, NBn*Dn*Dn);
    split_k<<<(NBn*Dn*Dn +255)/256,256>>>(whh, p_whhh, p_whhl, NBn*Dn*Dn);
    split_k<<<(NBn*Hn*Dn +255)/256,256>>>(dw1, p_dw1h, p_dw1l, NBn*Hn*Dn);
    split_k<<<(NBn*FINn*Hn+255)/256,256>>>(dw2, p_dw2h, p_dw2l, NBn*FINn*Hn);

    // ---- masked irfft as circulant GEMM: xi[nb,b] = T[nb] @ xnT[b]^T  (z = nb*256+b) ----
    mgemm_k<128,32,64,32,false,false><<<dim3(1, Ln/128, NBn*Bn), 64>>>(
        p_T, (size_t)Ln*Ln, Ln, 8,
        p_xnTh, p_xnTl, (size_t)Cn*Ln, Ln, 255,
        nullptr, 0, nullptr, 0, 0,
        p_xi, (size_t)Ln*Cn, Cn, Ln);

    // ---- HMMA weight GEMMs (validated R12) ----
    // enc L1: relu(xi @ ew1^T + eb1)
    mgemm_k<128,128,64,32,true,false><<<dim3(Hn/128, 16, NBn), 256>>>(
        p_xi, (size_t)Bn*Ln*Cn, FINn, 0,
        p_ew1h, p_ew1l, (size_t)Hn*FINn, FINn, 0x7fffffff,
        eb1, Hn, nullptr, 0, 0,
        p_enc1, (size_t)Bn*FREQn*Hn, Hn, FINn);

    // enc L2
    mgemm_k<128,128,64,32,false,false><<<dim3(Dn/128, 16, NBn), 256>>>(
        p_enc1, (size_t)Bn*FREQn*Hn, Hn, 0,
        p_ew2h, p_ew2l, (size_t)Dn*Hn, Hn, 0x7fffffff,
        eb2, Dn, nullptr, 0, 0,
        p_enc2, (size_t)Bn*FREQn*Dn, Dn, Hn);

    // encx = enc @ Wxh^T
    mgemm_k<128,128,64,32,false,false><<<dim3(Dn/128, 16, NBn), 256>>>(
        p_enc2, (size_t)Bn*FREQn*Dn, Dn, 0,
        p_wxhh, p_wxhl, (size_t)Dn*Dn, Dn, 0x7fffffff,
        nullptr, 0, nullptr, 0, 0,
        p_encx, (size_t)Bn*FREQn*Dn, Dn, Dn);

    // RNN: h_t = encx_t + h_{t-1} @ Whh^T
    for (int tau = 1; tau < FREQn; tau++) {
        const float* Ap; size_t sAv; int ldAv;
        if (tau == 1) { Ap = p_encx; sAv = (size_t)Bn*FREQn*Dn; ldAv = FREQn*Dn; }
        else if (tau % 2 == 0) { Ap = p_hA; sAv = (size_t)Bn*Dn; ldAv = Dn; }
        else { Ap = p_hB; sAv = (size_t)Bn*Dn; ldAv = Dn; }
        float* Cp = (tau % 2 == 1) ? p_hA : p_hB;
        mgemm_k<128,128,64,32,false,true><<<dim3(Dn/128, 2, NBn), 256>>>(
            Ap, sAv, ldAv, 0,
            p_whhh, p_whhl, (size_t)Dn*Dn, Dn, 0x7fffffff,
            nullptr, 0,
            p_encx + tau*Dn, (size_t)Bn*FREQn*Dn, FREQn*Dn,
            Cp, (size_t)Bn*Dn, Dn, Dn);
    }
    // free-run: preds_s = h @ Whh^T (chained)
    for (int s = 0; s < STEPn; s++) {
        const float* Ap; size_t sAv; int ldAv;
        if (s == 0) { Ap = p_hA; sAv = (size_t)Bn*Dn; ldAv = Dn; }
        else { Ap = p_preds + (s-1)*Dn; sAv = (size_t)Bn*STEPn*Dn; ldAv = STEPn*Dn; }
        mgemm_k<128,128,64,32,false,false><<<dim3(Dn/128, 2, NBn), 256>>>(
            Ap, sAv, ldAv, 0,
            p_whhh, p_whhl, (size_t)Dn*Dn, Dn, 0x7fffffff,
            nullptr, 0, nullptr, 0, 0,
            p_preds + s*Dn, (size_t)Bn*STEPn*Dn, STEPn*Dn, Dn);
    }

    ln_k<<<NBn*Bn*STEPn, 128>>>(lng, lnb);

    // dec L1: relu(preds @ dw1^T + db1)
    mgemm_k<128,128,64,32,true,false><<<dim3(Hn/128, 8, NBn), 256>>>(
        p_preds, (size_t)Bn*STEPn*Dn, Dn, 0,
        p_dw1h, p_dw1l, (size_t)Hn*Dn, Dn, 0x7fffffff,
        db1, Hn, nullptr, 0, 0,
        p_dec1, (size_t)Bn*STEPn*Hn, Hn, Dn);

    // dec L2
    mgemm_k<128,128,64,32,false,false><<<dim3(FINn/128, 8, NBn), 256>>>(
        p_dec1, (size_t)Bn*STEPn*Hn, Hn, 0,
        p_dw2h, p_dw2l, (size_t)FINn*Hn, Hn, 0x7fffffff,
        db2, FINn, nullptr, 0, 0,
        p_dec2, (size_t)Bn*STEPn*FINn, FINn, Hn);

    final_k<<<(Bn*STEPn*SEGn*Cn+255)/256, 256>>>(out);
}

// round 14
// speedup vs baseline: 4.2942x; 1.1577x over previous
#include <cuda_runtime.h>
#include <cuda_bf16.h>
#include <math.h>
#include <stdint.h>

// ---------------- problem dims ----------------
#define Bn   256
#define Ln   512
#define Cn   32
#define NBn  4
#define SEGn 64
#define FREQn 8
#define STEPn 4
#define Dn   512
#define Hn   1024
#define FINn 2048
#define Fn   257

// ---------------- scratch ----------------
__device__ float g_mean [Bn*Cn];
__device__ float g_std  [Bn*Cn];
__device__ float g_cf   [NBn*Fn];
__device__ float g_rho  [NBn*Ln];
__device__ float g_T    [(size_t)NBn*Ln*Ln];
__device__ float g_encx [(size_t)NBn*Bn*FREQn*Dn];
__device__ float g_dec2 [(size_t)NBn*Bn*STEPn*FINn];

#define BDECL(name, n) __device__ __align__(16) __nv_bfloat16 name##h[(size_t)(n)], name##l[(size_t)(n)]
BDECL(g_T16,  NBn*Ln*Ln);
BDECL(g_xnT,  Bn*Cn*Ln);
BDECL(g_xi,   (size_t)NBn*Bn*Ln*Cn);
BDECL(g_enc1, (size_t)NBn*Bn*FREQn*Hn);
BDECL(g_enc2, (size_t)NBn*Bn*FREQn*Dn);
BDECL(g_encx16, (size_t)NBn*Bn*FREQn*Dn);
BDECL(g_hA,   NBn*Bn*Dn);
BDECL(g_hB,   NBn*Bn*Dn);
BDECL(g_preds, NBn*Bn*STEPn*Dn);
BDECL(g_dec1, (size_t)NBn*Bn*STEPn*Hn);
BDECL(g_ew1,  (size_t)NBn*Hn*FINn);
BDECL(g_ew2,  (size_t)NBn*Dn*Hn);
BDECL(g_wxh,  NBn*Dn*Dn);
BDECL(g_whh,  NBn*Dn*Dn);
BDECL(g_dw1,  (size_t)NBn*Hn*Dn);
BDECL(g_dw2,  (size_t)NBn*FINn*Hn);

// ---------------- prep kernels ----------------
__global__ void cf_k(const float* __restrict__ mw) {
    int i = blockIdx.x * 256 + threadIdx.x;
    if (i < NBn * Fn) g_cf[i] = 1.f / (1.f + expf(-mw[i]));
}
__global__ void rho_k() {
    int nb = blockIdx.x, d = threadIdx.x;
    const float* cf = g_cf + nb * Fn;
    const float ST = 6.28318530717958647692f / 512.f;
    float s = cf[0] + ((d & 1) ? -cf[256] : cf[256]);
    for (int k = 1; k <= 255; k++)
        s += 2.f * cf[k] * cosf((float)((k * d) & 511) * ST);
    g_rho[nb * Ln + d] = s * (1.f / 512.f);
}
__global__ void tbuild_k() {
    int i = blockIdx.x * 256 + threadIdx.x;
    int nb = i >> 18, t = (i >> 9) & 511, tp = i & 511;
    g_T[i] = g_rho[nb * Ln + ((t - tp) & 511)];
}
__global__ void split_k(const float* __restrict__ s, __nv_bfloat16* __restrict__ h,
                        __nv_bfloat16* __restrict__ l, int n) {
    int i = blockIdx.x * 256 + threadIdx.x;
    if (i >= n) return;
    float v = s[i];
    __nv_bfloat16 hh = __float2bfloat16(v);
    h[i] = hh;
    l[i] = __float2bfloat16(v - __bfloat162float(hh));
}

// ---------------- instance norm + transposed split-bf16 write ----------------
__global__ void instnorm_k(const float* __restrict__ x) {
    int b = blockIdx.x;
    int c = threadIdx.x & 31, r = threadIdx.x >> 5;
    const float* xb = x + (size_t)b * Ln * Cn;
    float s = 0.f, sq = 0.f;
    for (int t = r; t < Ln; t += 8) { float v = xb[t * Cn + c]; s += v; sq += v * v; }
    __shared__ float ss[8][32], sg[8][32], smean[32], srstd[32];
    ss[r][c] = s; sg[r][c] = sq;
    __syncthreads();
    if (threadIdx.x < 32) {
        float a = 0.f, q = 0.f;
        #pragma unroll
        for (int j = 0; j < 8; j++) { a += ss[j][threadIdx.x]; q += sg[j][threadIdx.x]; }
        float m = a * (1.f / 512.f);
        float var = q * (1.f / 512.f) - m * m;
        float sd = sqrtf(var + 1e-5f);
        g_mean[b * Cn + threadIdx.x] = m;
        g_std [b * Cn + threadIdx.x] = sd;
        smean[threadIdx.x] = m; srstd[threadIdx.x] = 1.f / sd;
    }
    __syncthreads();
    __shared__ float tile[256][33];
    for (int t0 = 0; t0 < Ln; t0 += 256) {
        for (int idx = threadIdx.x; idx < 256 * 32; idx += 256) {
            int t = idx >> 5, cc = idx & 31;
            tile[t][cc] = (xb[(t0 + t) * Cn + cc] - smean[cc]) * srstd[cc];
        }
        __syncthreads();
        for (int idx = threadIdx.x; idx < 32 * 256; idx += 256) {
            int cc = idx >> 8, t = idx & 255;
            float v = tile[t][cc];
            __nv_bfloat16 h = __float2bfloat16(v);
            size_t o = (size_t)b * Cn * Ln + (size_t)cc * Ln + t0 + t;
            g_xnTh[o] = h;
            g_xnTl[o] = __float2bfloat16(v - __bfloat162float(h));
        }
        __syncthreads();
    }
}

// ---------------- cp.async helpers ----------------
__device__ __forceinline__ void cpa16(uint32_t dst, const void* src) {
    asm volatile("cp.async.cg.shared.global [%0], [%1], 16;" :: "r"(dst), "l"(src));
}
#define CP_COMMIT() asm volatile("cp.async.commit_group;" ::: "memory")
#define CP_WAIT1()  asm volatile("cp.async.wait_group 1;" ::: "memory")
#define CP_WAIT0()  asm volatile("cp.async.wait_group 0;" ::: "memory")

#define MMA_OP(c, a0, a1, a2, a3, b0, b1) \
    asm volatile("mma.sync.aligned.m16n8k16.row.col.f32.bf16.bf16.f32 " \
        "{%0,%1,%2,%3}, {%4,%5,%6,%7}, {%8,%9}, {%0,%1,%2,%3};" \
        : "+f"((c)[0]), "+f"((c)[1]), "+f"((c)[2]), "+f"((c)[3]) \
        : "r"(a0), "r"(a1), "r"(a2), "r"(a3), "r"(b0), "r"(b1))

// ---------------- double-buffered split-bf16 HMMA GEMM ----------------
// C = act(Asplit @ Bsplit^T + bias (+E)); A [M,K] bf16 hi/lo, B [N,K] bf16 hi/lo.
// 3-MMA compensation: AhBh + AlBh + AhBl (fp32 accum). Outputs: fp32 and/or hi/lo split.
// XIOUT: special epilogue layout for the irfft (C[t,(b,c)] -> xi[b][t][c]).
template<int BM,int BN,int WM,int WN,bool RELU,bool HASE,bool WF32,bool WSPLIT,bool XIOUT>
__global__ void __launch_bounds__((BM/WM)*(BN/WN)*32, 2)
mgemm2_k(const __nv_bfloat16* __restrict__ Ah, const __nv_bfloat16* __restrict__ Al,
         size_t sA, int ldA, int zAs,
         const __nv_bfloat16* __restrict__ Bh, const __nv_bfloat16* __restrict__ Bl,
         size_t sB, int ldB, int zBm,
         const float* __restrict__ bias, int sBias,
         const float* __restrict__ E, size_t sE, int ldE,
         float* __restrict__ C, __nv_bfloat16* __restrict__ Ch, __nv_bfloat16* __restrict__ Cl,
         size_t sC, int ldC, int K)
{
    constexpr int NWARP = (BM/WM)*(BN/WN);
    constexpr int NT = NWARP * 32;
    constexpr int PAD = 40;
    constexpr int MF = WM / 16, NF = WN / 8;
    constexpr int ABYTES = BM * PAD * 2;
    constexpr int BBYTES = BN * PAD * 2;
    constexpr int STG = 2 * ABYTES + 2 * BBYTES;

    extern __shared__ char dsm[];
    uint32_t smem_base = (uint32_t)__cvta_generic_to_shared(dsm);

    int tid = threadIdx.x, warp = tid >> 5, lane = tid & 31;
    int z = blockIdx.z, m0 = blockIdx.y * BM, n0 = blockIdx.x * BN;

    Ah += (size_t)(z >> zAs) * sA + (size_t)m0 * ldA;
    Al += (size_t)(z >> zAs) * sA + (size_t)m0 * ldA;
    Bh += (size_t)(z & zBm) * sB + (size_t)n0 * ldB;
    Bl += (size_t)(z & zBm) * sB + (size_t)n0 * ldB;

    int wm = warp % (BM / WM), wn = warp / (BM / WM);
    int mB = wm * WM, nB = wn * WN;

    float acc[MF][NF][4];
    #pragma unroll
    for (int i = 0; i < MF; i++)
        #pragma unroll
        for (int j = 0; j < NF; j++)
            #pragma unroll
            for (int q = 0; q < 4; q++) acc[i][j][q] = 0.f;

    const int nk = K / 32;
    auto issue = [&](int kt, int stg) {
        int k0 = kt * 32;
        uint32_t base = smem_base + stg * STG;
        #pragma unroll
        for (int j = 0; j < BM * 4 / NT; j++) {
            int idx = tid + j * NT;
            int row = idx >> 2, c8 = idx & 3;
            uint32_t d = base + (uint32_t)(row * PAD + c8 * 8) * 2;
            const __nv_bfloat16* sh = Ah + (size_t)row * ldA + k0 + c8 * 8;
            const __nv_bfloat16* sl = Al + (size_t)row * ldA + k0 + c8 * 8;
            cpa16(d, sh);
            cpa16(d + ABYTES, sl);
        }
        #pragma unroll
        for (int j = 0; j < BN * 4 / NT; j++) {
            int idx = tid + j * NT;
            int row = idx >> 2, c8 = idx & 3;
            uint32_t d = base + 2 * ABYTES + (uint32_t)(row * PAD + c8 * 8) * 2;
            const __nv_bfloat16* sh = Bh + (size_t)row * ldB + k0 + c8 * 8;
            const __nv_bfloat16* sl = Bl + (size_t)row * ldB + k0 + c8 * 8;
            cpa16(d, sh);
            cpa16(d + BBYTES, sl);
        }
    };

    issue(0, 0);
    CP_COMMIT();

    for (int kt = 0; kt < nk; kt++) {
        int cur = kt & 1;
        if (kt + 1 < nk) {
            issue(kt + 1, cur ^ 1);
            CP_COMMIT();
            CP_WAIT1();
        } else {
            CP_WAIT0();
        }
        __syncthreads();

        const __nv_bfloat16* sAh = (const __nv_bfloat16*)(dsm + cur * STG);
        const __nv_bfloat16* sAl = sAh + BM * PAD;
        const __nv_bfloat16* sBh = (const __nv_bfloat16*)(dsm + cur * STG + 2 * ABYTES);
        const __nv_bfloat16* sBl = sBh + BN * PAD;

        #pragma unroll
        for (int ks = 0; ks < 32; ks += 16) {
            int kk = ks + (lane & 3) * 2;
            int r0 = mB + (lane >> 2);
            uint32_t ah[MF][4], al[MF][4];
            #pragma unroll
            for (int mf = 0; mf < MF; mf++) {
                int r = r0 + mf * 16;
                ah[mf][0] = *reinterpret_cast<const uint32_t*>(&sAh[r * PAD + kk]);
                ah[mf][1] = *reinterpret_cast<const uint32_t*>(&sAh[(r + 8) * PAD + kk]);
                ah[mf][2] = *reinterpret_cast<const uint32_t*>(&sAh[r * PAD + kk + 8]);
                ah[mf][3] = *reinterpret_cast<const uint32_t*>(&sAh[(r + 8) * PAD + kk + 8]);
                al[mf][0] = *reinterpret_cast<const uint32_t*>(&sAl[r * PAD + kk]);
                al[mf][1] = *reinterpret_cast<const uint32_t*>(&sAl[(r + 8) * PAD + kk]);
                al[mf][2] = *reinterpret_cast<const uint32_t*>(&sAl[r * PAD + kk + 8]);
                al[mf][3] = *reinterpret_cast<const uint32_t*>(&sAl[(r + 8) * PAD + kk + 8]);
            }
            #pragma unroll
            for (int nf = 0; nf < NF; nf++) {
                int cB = nB + nf * 8 + (lane >> 2);
                uint32_t bh0 = *reinterpret_cast<const uint32_t*>(&sBh[cB * PAD + kk]);
                uint32_t bh1 = *reinterpret_cast<const uint32_t*>(&sBh[cB * PAD + kk + 8]);
                uint32_t bl0 = *reinterpret_cast<const uint32_t*>(&sBl[cB * PAD + kk]);
                uint32_t bl1 = *reinterpret_cast<const uint32_t*>(&sBl[cB * PAD + kk + 8]);
                #pragma unroll
                for (int mf = 0; mf < MF; mf++) {
                    MMA_OP(acc[mf][nf], ah[mf][0], ah[mf][1], ah[mf][2], ah[mf][3], bh0, bh1);
                    MMA_OP(acc[mf][nf], al[mf][0], al[mf][1], al[mf][2], al[mf][3], bh0, bh1);
                    MMA_OP(acc[mf][nf], ah[mf][0], ah[mf][1], ah[mf][2], ah[mf][3], bl0, bl1);
                }
            }
        }
        __syncthreads();
    }

    // ---- epilogue ----
    if (!XIOUT) {
        size_t cb = (size_t)z * sC + (size_t)m0 * ldC + n0;
        if (WF32) C += cb;
        if (WSPLIT) { Ch += cb; Cl += cb; }
    } else {
        Ch += (size_t)z * sC;
        Cl += (size_t)z * sC;
    }
    if (HASE) E += (size_t)z * sE + (size_t)m0 * ldE + n0;

    #pragma unroll
    for (int mf = 0; mf < MF; mf++) {
        #pragma unroll
        for (int nf = 0; nf < NF; nf++) {
            int r = mB + mf * 16 + (lane >> 2);
            int cc = nB + nf * 8 + (lane & 3) * 2;
            float b0 = 0.f, b1 = 0.f;
            if (bias) {
                b0 = bias[(size_t)z * sBias + n0 + cc];
                b1 = bias[(size_t)z * sBias + n0 + cc + 1];
            }
            float v0 = acc[mf][nf][0] + b0, v1 = acc[mf][nf][1] + b1;
            float v2 = acc[mf][nf][2] + b0, v3 = acc[mf][nf][3] + b1;
            if (HASE) {
                v0 += E[(size_t)r * ldE + cc];       v1 += E[(size_t)r * ldE + cc + 1];
                v2 += E[(size_t)(r + 8) * ldE + cc]; v3 += E[(size_t)(r + 8) * ldE + cc + 1];
            }
            if (RELU) {
                v0 = fmaxf(v0, 0.f); v1 = fmaxf(v1, 0.f);
                v2 = fmaxf(v2, 0.f); v3 = fmaxf(v3, 0.f);
            }
            if (WF32 && !XIOUT) {
                *reinterpret_cast<float2*>(&C[(size_t)r * ldC + cc]) = make_float2(v0, v1);
                *reinterpret_cast<float2*>(&C[(size_t)(r + 8) * ldC + cc]) = make_float2(v2, v3);
            }
            if (WSPLIT || XIOUT) {
                __nv_bfloat162 h01 = __float22bfloat162_rn(make_float2(v0, v1));
                float2 hr01 = __bfloat1622float2(h01);
                __nv_bfloat162 l01 = __float22bfloat162_rn(make_float2(v0 - hr01.x, v1 - hr01.y));
                __nv_bfloat162 h23 = __float22bfloat162_rn(make_float2(v2, v3));
                float2 hr23 = __bfloat1622float2(h23);
                __nv_bfloat162 l23 = __float22bfloat162_rn(make_float2(v2 - hr23.x, v3 - hr23.y));
                if (XIOUT) {
                    int n = n0 + cc;
                    size_t o0 = (size_t)(n >> 5) * (Ln * Cn) + (size_t)(m0 + r) * Cn + (n & 31);
                    size_t o2 = o0 + 8 * Cn;
                    *reinterpret_cast<__nv_bfloat162*>(&Ch[o0]) = h01;
                    *reinterpret_cast<__nv_bfloat162*>(&Cl[o0]) = l01;
                    *reinterpret_cast<__nv_bfloat162*>(&Ch[o2]) = h23;
                    *reinterpret_cast<__nv_bfloat162*>(&Cl[o2]) = l23;
                } else {
                    *reinterpret_cast<__nv_bfloat162*>(&Ch[(size_t)r * ldC + cc]) = h01;
                    *reinterpret_cast<__nv_bfloat162*>(&Cl[(size_t)r * ldC + cc]) = l01;
                    *reinterpret_cast<__nv_bfloat162*>(&Ch[(size_t)(r + 8) * ldC + cc]) = h23;
                    *reinterpret_cast<__nv_bfloat162*>(&Cl[(size_t)(r + 8) * ldC + cc]) = l23;
                }
            }
        }
    }
}

// ---------------- LayerNorm over D (hi/lo in-place) ----------------
__global__ void ln_k(const float* __restrict__ g, const float* __restrict__ bb) {
    int row = blockIdx.x;
    int nb = row >> 10;
    __nv_bfloat16* ph = g_predsh + (size_t)row * Dn;
    __nv_bfloat16* pl = g_predsl + (size_t)row * Dn;
    int tid = threadIdx.x;
    float v[4];
    float s = 0.f, sq = 0.f;
    #pragma unroll
    for (int j = 0; j < 4; j++) {
        int d = tid + j * 128;
        v[j] = __bfloat162float(ph[d]) + __bfloat162float(pl[d]);
        s += v[j]; sq += v[j] * v[j];
    }
    #pragma unroll
    for (int off = 16; off > 0; off >>= 1) {
        s  += __shfl_xor_sync(0xffffffffu, s, off);
        sq += __shfl_xor_sync(0xffffffffu, sq, off);
    }
    __shared__ float rs[4], rq[4];
    if ((tid & 31) == 0) { rs[tid >> 5] = s; rq[tid >> 5] = sq; }
    __syncthreads();
    s = rs[0] + rs[1] + rs[2] + rs[3];
    sq = rq[0] + rq[1] + rq[2] + rq[3];
    float mean = s * (1.f / 512.f);
    float var = sq * (1.f / 512.f) - mean * mean;
    float rstd = rsqrtf(var + 1e-5f);
    #pragma unroll
    for (int j = 0; j < 4; j++) {
        int d = tid + j * 128;
        float o = (v[j] - mean) * rstd * g[nb * Dn + d] + bb[nb * Dn + d];
        __nv_bfloat16 h = __float2bfloat16(o);
        ph[d] = h;
        pl[d] = __float2bfloat16(o - __bfloat162float(h));
    }
}

// ---------------- final: sum blocks, de-normalize ----------------
__global__ void final_k(float* __restrict__ out) {
    size_t i = (size_t)blockIdx.x * 256 + threadIdx.x;
    const size_t TOT = (size_t)Bn * STEPn * SEGn * Cn;
    if (i >= TOT) return;
    int b = (int)(i >> 13);
    int c = (int)(i & 31);
    float a = g_dec2[i] + g_dec2[i + TOT] + g_dec2[i + 2 * TOT] + g_dec2[i + 3 * TOT];
    out[i] = a * g_std[b * Cn + c] + g_mean[b * Cn + c];
}

// ---------------- host ----------------
static inline void* symp(const void* s) { void* p; cudaGetSymbolAddress(&p, s); return p; }

extern "C" void kernel_launch(void* const* d_in, const int* in_sizes, int n_in,
                              void* d_out, int out_size) {
    const float* x_enc = (const float*)d_in[0];
    const float* mw  = (const float*)d_in[4];
    const float* ew1 = (const float*)d_in[5];
    const float* eb1 = (const float*)d_in[6];
    const float* ew2 = (const float*)d_in[7];
    const float* eb2 = (const float*)d_in[8];
    const float* wxh = (const float*)d_in[9];
    const float* whh = (const float*)d_in[10];
    const float* lng = (const float*)d_in[11];
    const float* lnb = (const float*)d_in[12];
    const float* dw1 = (const float*)d_in[13];
    const float* db1 = (const float*)d_in[14];
    const float* dw2 = (const float*)d_in[15];
    const float* db2 = (const float*)d_in[16];
    float* out = (float*)d_out;

    float* p_T    = (float*)symp(g_T);
    float* p_encx = (float*)symp(g_encx);
    float* p_dec2 = (float*)symp(g_dec2);
    typedef __nv_bfloat16 bf;
#define SYM2(nm) bf* p_##nm##h = (bf*)symp(g_##nm##h); bf* p_##nm##l = (bf*)symp(g_##nm##l)
    SYM2(T16); SYM2(xnT); SYM2(xi); SYM2(enc1); SYM2(enc2); SYM2(encx16);
    SYM2(hA); SYM2(hB); SYM2(preds); SYM2(dec1);
    SYM2(ew1); SYM2(ew2); SYM2(wxh); SYM2(whh); SYM2(dw1); SYM2(dw2);

    const int SMEMB = 2 * (2 * 128 * 40 * 2 + 2 * 128 * 40 * 2);  // 81920
    auto* fXI  = mgemm2_k<128,128,64,32,false,false,false,true,true>;
    auto* fRS  = mgemm2_k<128,128,64,32,true, false,false,true,false>;
    auto* fS   = mgemm2_k<128,128,64,32,false,false,false,true,false>;
    auto* fES  = mgemm2_k<128,128,64,32,false,true, false,true,false>;
    auto* fFS  = mgemm2_k<128,128,64,32,false,false,true, true,false>;
    auto* fF   = mgemm2_k<128,128,64,32,false,false,true, false,false>;
    cudaFuncSetAttribute((const void*)fXI, cudaFuncAttributeMaxDynamicSharedMemorySize, SMEMB);
    cudaFuncSetAttribute((const void*)fRS, cudaFuncAttributeMaxDynamicSharedMemorySize, SMEMB);
    cudaFuncSetAttribute((const void*)fS,  cudaFuncAttributeMaxDynamicSharedMemorySize, SMEMB);
    cudaFuncSetAttribute((const void*)fES, cudaFuncAttributeMaxDynamicSharedMemorySize, SMEMB);
    cudaFuncSetAttribute((const void*)fFS, cudaFuncAttributeMaxDynamicSharedMemorySize, SMEMB);
    cudaFuncSetAttribute((const void*)fF,  cudaFuncAttributeMaxDynamicSharedMemorySize, SMEMB);

    // ---- prep ----
    cf_k    <<<5, 256>>>(mw);
    rho_k   <<<NBn, 512>>>();
    tbuild_k<<<4096, 256>>>();
    instnorm_k<<<Bn, 256>>>(x_enc);

    split_k<<<(NBn*Ln*Ln +255)/256,256>>>(p_T, p_T16h, p_T16l, NBn*Ln*Ln);
    split_k<<<(NBn*Hn*FINn+255)/256,256>>>(ew1, p_ew1h, p_ew1l, NBn*Hn*FINn);
    split_k<<<(NBn*Dn*Hn +255)/256,256>>>(ew2, p_ew2h, p_ew2l, NBn*Dn*Hn);
    split_k<<<(NBn*Dn*Dn +255)/256,256>>>(wxh, p_wxhh, p_wxhl, NBn*Dn*Dn);
    split_k<<<(NBn*Dn*Dn +255)/256,256>>>(whh, p_whhh, p_whhl, NBn*Dn*Dn);
    split_k<<<(NBn*Hn*Dn +255)/256,256>>>(dw1, p_dw1h, p_dw1l, NBn*Hn*Dn);
    split_k<<<(NBn*FINn*Hn+255)/256,256>>>(dw2, p_dw2h, p_dw2l, NBn*FINn*Hn);

    // ---- irfft: xi[nb] = T16[nb] @ xnT^T  (z = nb; XIOUT layout) ----
    fXI<<<dim3((Bn*Cn)/128, Ln/128, NBn), 256, SMEMB>>>(
        p_T16h, p_T16l, (size_t)Ln*Ln, Ln, 0,
        p_xnTh, p_xnTl, 0, Ln, 0,
        nullptr, 0, nullptr, 0, 0,
        nullptr, p_xih, p_xil, (size_t)Bn*Ln*Cn, Cn, Ln);

    // ---- enc L1: relu(xi @ ew1^T + eb1) ----
    fRS<<<dim3(Hn/128, (Bn*FREQn)/128, NBn), 256, SMEMB>>>(
        p_xih, p_xil, (size_t)Bn*Ln*Cn, FINn, 0,
        p_ew1h, p_ew1l, (size_t)Hn*FINn, FINn, 0x7fffffff,
        eb1, Hn, nullptr, 0, 0,
        nullptr, p_enc1h, p_enc1l, (size_t)Bn*FREQn*Hn, Hn, FINn);

    // ---- enc L2 ----
    fS<<<dim3(Dn/128, (Bn*FREQn)/128, NBn), 256, SMEMB>>>(
        p_enc1h, p_enc1l, (size_t)Bn*FREQn*Hn, Hn, 0,
        p_ew2h, p_ew2l, (size_t)Dn*Hn, Hn, 0x7fffffff,
        eb2, Dn, nullptr, 0, 0,
        nullptr, p_enc2h, p_enc2l, (size_t)Bn*FREQn*Dn, Dn, Hn);

    // ---- encx = enc @ Wxh^T (fp32 for E-reads + split for A at tau=1) ----
    fFS<<<dim3(Dn/128, (Bn*FREQn)/128, NBn), 256, SMEMB>>>(
        p_enc2h, p_enc2l, (size_t)Bn*FREQn*Dn, Dn, 0,
        p_wxhh, p_wxhl, (size_t)Dn*Dn, Dn, 0x7fffffff,
        nullptr, 0, nullptr, 0, 0,
        p_encx, p_encx16h, p_encx16l, (size_t)Bn*FREQn*Dn, Dn, Dn);

    // ---- RNN: h_t = encx_t + h_{t-1} @ Whh^T ----
    for (int tau = 1; tau < FREQn; tau++) {
        const bf *Aph, *Apl; size_t sAv; int ldAv;
        if (tau == 1) { Aph = p_encx16h; Apl = p_encx16l; sAv = (size_t)Bn*FREQn*Dn; ldAv = FREQn*Dn; }
        else if (tau % 2 == 0) { Aph = p_hAh; Apl = p_hAl; sAv = (size_t)Bn*Dn; ldAv = Dn; }
        else { Aph = p_hBh; Apl = p_hBl; sAv = (size_t)Bn*Dn; ldAv = Dn; }
        bf* Cph = (tau % 2 == 1) ? p_hAh : p_hBh;
        bf* Cpl = (tau % 2 == 1) ? p_hAl : p_hBl;
        fES<<<dim3(Dn/128, Bn/128, NBn), 256, SMEMB>>>(
            Aph, Apl, sAv, ldAv, 0,
            p_whhh, p_whhl, (size_t)Dn*Dn, Dn, 0x7fffffff,
            nullptr, 0,
            p_encx + tau*Dn, (size_t)Bn*FREQn*Dn, FREQn*Dn,
            nullptr, Cph, Cpl, (size_t)Bn*Dn, Dn, Dn);
    }
    // ---- free-run: preds_s = h @ Whh^T (chained; h in hA) ----
    for (int s = 0; s < STEPn; s++) {
        const bf *Aph, *Apl; size_t sAv; int ldAv;
        if (s == 0) { Aph = p_hAh; Apl = p_hAl; sAv = (size_t)Bn*Dn; ldAv = Dn; }
        else { Aph = p_predsh + (s-1)*Dn; Apl = p_predsl + (s-1)*Dn; sAv = (size_t)Bn*STEPn*Dn; ldAv = STEPn*Dn; }
        fS<<<dim3(Dn/128, Bn/128, NBn), 256, SMEMB>>>(
            Aph, Apl, sAv, ldAv, 0,
            p_whhh, p_whhl, (size_t)Dn*Dn, Dn, 0x7fffffff,
            nullptr, 0, nullptr, 0, 0,
            nullptr, p_predsh + s*Dn, p_predsl + s*Dn, (size_t)Bn*STEPn*Dn, STEPn*Dn, Dn);
    }

    ln_k<<<NBn*Bn*STEPn, 128>>>(lng, lnb);

    // ---- dec L1: relu(preds @ dw1^T + db1) ----
    fRS<<<dim3(Hn/128, (Bn*STEPn)/128, NBn), 256, SMEMB>>>(
        p_predsh, p_predsl, (size_t)Bn*STEPn*Dn, Dn, 0,
        p_dw1h, p_dw1l, (size_t)Hn*Dn, Dn, 0x7fffffff,
        db1, Hn, nullptr, 0, 0,
        nullptr, p_dec1h, p_dec1l, (size_t)Bn*STEPn*Hn, Hn, Dn);

    // ---- dec L2 (fp32 out for final_k) ----
    fF<<<dim3(FINn/128, (Bn*STEPn)/128, NBn), 256, SMEMB>>>(
        p_dec1h, p_dec1l, (size_t)Bn*STEPn*Hn, Hn, 0,
        p_dw2h, p_dw2l, (size_t)FINn*Hn, Hn, 0x7fffffff,
        db2, FINn, nullptr, 0, 0,
        p_dec2, nullptr, nullptr, (size_t)Bn*STEPn*FINn, FINn, Hn);

    final_k<<<(Bn*STEPn*SEGn*Cn + 255)/256, 256>>>(out);
}